// round 1
// baseline (speedup 1.0000x reference)
#include <cuda_runtime.h>

#define BSZ  4
#define TSEQ 2048
#define CDIM 1024
#define HH   16
#define DHEAD 64
#define MROWS (BSZ*TSEQ)   // 8192

// Scratch (allocation-free rule: device globals)
__device__ float g_q[(size_t)BSZ*HH*TSEQ*DHEAD];
__device__ float g_k[(size_t)BSZ*HH*TSEQ*DHEAD];
__device__ float g_v[(size_t)BSZ*HH*TSEQ*DHEAD];
__device__ float g_att[(size_t)MROWS*CDIM];

// ---------------------------------------------------------------------------
// Tiled SGEMM: C[M,N] = A[M,K] @ B[K,N] + bias
// BM=BN=64, BK=16, 256 threads, 4x4 register tile per thread.
// mode 0: A = x, scatter into g_q/g_k/g_v ([B,H,T,Dh]) with bias
// mode 1: A = g_att, write to Cout with bias
// ---------------------------------------------------------------------------
__global__ __launch_bounds__(256)
void sgemm_kernel(const float* __restrict__ A, const float* __restrict__ Bw,
                  const float* __restrict__ bias, float* __restrict__ Cout,
                  int N, int K, int mode)
{
    __shared__ float As[16][64];   // transposed A tile
    __shared__ float Bs[16][64];

    const int tid = threadIdx.x;
    const int tx = tid & 15, ty = tid >> 4;
    const int m0 = blockIdx.y * 64, n0 = blockIdx.x * 64;

    if (mode == 1) A = g_att;

    float acc[4][4];
#pragma unroll
    for (int i = 0; i < 4; i++)
#pragma unroll
        for (int j = 0; j < 4; j++) acc[i][j] = 0.f;

    const int aRow = tid >> 2, aC4 = tid & 3;     // A tile: 64 rows x 16 cols
    const int bRow = tid >> 4, bC4 = tid & 15;    // B tile: 16 rows x 64 cols

    for (int k0 = 0; k0 < K; k0 += 16) {
        float4 av = *(const float4*)(A + (size_t)(m0 + aRow) * K + k0 + aC4 * 4);
        float4 bv = *(const float4*)(Bw + (size_t)(k0 + bRow) * N + n0 + bC4 * 4);
        As[aC4*4+0][aRow] = av.x;
        As[aC4*4+1][aRow] = av.y;
        As[aC4*4+2][aRow] = av.z;
        As[aC4*4+3][aRow] = av.w;
        *(float4*)(&Bs[bRow][bC4*4]) = bv;
        __syncthreads();
#pragma unroll
        for (int kk = 0; kk < 16; kk++) {
            float4 a = *(const float4*)(&As[kk][ty*4]);
            float4 b = *(const float4*)(&Bs[kk][tx*4]);
            acc[0][0] += a.x*b.x; acc[0][1] += a.x*b.y; acc[0][2] += a.x*b.z; acc[0][3] += a.x*b.w;
            acc[1][0] += a.y*b.x; acc[1][1] += a.y*b.y; acc[1][2] += a.y*b.z; acc[1][3] += a.y*b.w;
            acc[2][0] += a.z*b.x; acc[2][1] += a.z*b.y; acc[2][2] += a.z*b.z; acc[2][3] += a.z*b.w;
            acc[3][0] += a.w*b.x; acc[3][1] += a.w*b.y; acc[3][2] += a.w*b.z; acc[3][3] += a.w*b.w;
        }
        __syncthreads();
    }

    if (mode == 0) {
        // n0 is 64-aligned: whole tile belongs to one section (q/k/v) and one head
        const int sec = n0 >> 10;          // 0,1,2
        const int cc  = n0 & 1023;
        const int h   = cc >> 6;
        float* dst = (sec == 0) ? g_q : ((sec == 1) ? g_k : g_v);
#pragma unroll
        for (int i = 0; i < 4; i++) {
            const int r = m0 + ty*4 + i;
            const int b = r >> 11, t = r & 2047;
            float* row = dst + (((size_t)(b*HH + h))*TSEQ + t)*DHEAD;
#pragma unroll
            for (int j = 0; j < 4; j++) {
                const int col = n0 + tx*4 + j;
                row[tx*4 + j] = acc[i][j] + bias[col];
            }
        }
    } else {
#pragma unroll
        for (int i = 0; i < 4; i++) {
            const int r = m0 + ty*4 + i;
#pragma unroll
            for (int j = 0; j < 4; j++) {
                const int col = n0 + tx*4 + j;
                Cout[(size_t)r * N + col] = acc[i][j] + bias[col];
            }
        }
    }
}

// ---------------------------------------------------------------------------
// Flash-attention fp32, causal. 1 thread = 1 query row, BM=BN=64.
// Q,K stored transposed [d][row] with XOR swizzle (row ^ (d&28)):
//   - scalar q reads: lanes consecutive-after-XOR -> conflict-free
//   - vector K reads: broadcast (all lanes same addr) -> conflict-free
//   - transpose STS: 2-way conflict only
// V stored [j][d4] as float4, broadcast reads.
// ---------------------------------------------------------------------------
__global__ __launch_bounds__(64)
void attn_kernel()
{
    __shared__ float  Qs[64*64];
    __shared__ float  Ks[64*64];
    __shared__ float4 Vs[64*16];

    const int tid = threadIdx.x;                 // query row within tile
    const int bh  = blockIdx.y;                  // b*H + h
    const int qt  = (gridDim.x - 1) - blockIdx.x; // long blocks first
    const int q0  = qt * 64;

    const float* Qg = g_q + (size_t)bh * TSEQ * DHEAD;
    const float* Kg = g_k + (size_t)bh * TSEQ * DHEAD;
    const float* Vg = g_v + (size_t)bh * TSEQ * DHEAD;

    // Load Q tile, pre-scaled by 1/sqrt(Dh), transposed + swizzled
    for (int f = tid; f < 1024; f += 64) {
        const int i = f >> 4, d4 = f & 15;
        float4 v = *(const float4*)(Qg + (size_t)(q0 + i)*DHEAD + d4*4);
        const int db = d4*4, sw = db & 28, ix = i ^ sw;
        Qs[(db+0)*64 + ix] = v.x * 0.125f;
        Qs[(db+1)*64 + ix] = v.y * 0.125f;
        Qs[(db+2)*64 + ix] = v.z * 0.125f;
        Qs[(db+3)*64 + ix] = v.w * 0.125f;
    }

    float m = -1e30f, l = 0.f;
    float4 O[16];
#pragma unroll
    for (int d4 = 0; d4 < 16; d4++) O[d4] = make_float4(0.f, 0.f, 0.f, 0.f);

    const int qg = q0 + tid;

    for (int jt = 0; jt <= qt; jt++) {
        const int j0 = jt * 64;
        __syncthreads();
        // Load K (transposed+swizzled) and V tiles
        for (int f = tid; f < 1024; f += 64) {
            const int j = f >> 4, d4 = f & 15;
            float4 kv = *(const float4*)(Kg + (size_t)(j0 + j)*DHEAD + d4*4);
            const int db = d4*4, sw = db & 28, jx = j ^ sw;
            Ks[(db+0)*64 + jx] = kv.x;
            Ks[(db+1)*64 + jx] = kv.y;
            Ks[(db+2)*64 + jx] = kv.z;
            Ks[(db+3)*64 + jx] = kv.w;
            Vs[j*16 + d4] = *(const float4*)(Vg + (size_t)(j0 + j)*DHEAD + d4*4);
        }
        __syncthreads();

        // S = Q K^T (this thread's row)
        float4 s4[16];
#pragma unroll
        for (int j4 = 0; j4 < 16; j4++) s4[j4] = make_float4(0.f, 0.f, 0.f, 0.f);

#pragma unroll 4
        for (int d = 0; d < 64; d++) {
            const float qd = Qs[d*64 + (tid ^ (d & 28))];
            const float4* kr = (const float4*)Ks + d*16;
            const int sw4 = (d & 28) >> 2;
#pragma unroll
            for (int j4 = 0; j4 < 16; j4++) {
                float4 kk = kr[j4 ^ sw4];
                s4[j4].x += qd * kk.x;
                s4[j4].y += qd * kk.y;
                s4[j4].z += qd * kk.z;
                s4[j4].w += qd * kk.w;
            }
        }

        // Causal mask (only the diagonal tile needs it)
        if (jt == qt) {
#pragma unroll
            for (int j4 = 0; j4 < 16; j4++) {
                const int jb = j0 + j4*4;
                if (jb + 0 > qg) s4[j4].x = -1e30f;
                if (jb + 1 > qg) s4[j4].y = -1e30f;
                if (jb + 2 > qg) s4[j4].z = -1e30f;
                if (jb + 3 > qg) s4[j4].w = -1e30f;
            }
        }

        // Online softmax
        float mnew = m;
#pragma unroll
        for (int j4 = 0; j4 < 16; j4++) {
            mnew = fmaxf(mnew, fmaxf(fmaxf(s4[j4].x, s4[j4].y), fmaxf(s4[j4].z, s4[j4].w)));
        }
        const float corr = __expf(m - mnew);
        l *= corr;
#pragma unroll
        for (int d4 = 0; d4 < 16; d4++) {
            O[d4].x *= corr; O[d4].y *= corr; O[d4].z *= corr; O[d4].w *= corr;
        }

        float lsum = 0.f;
#pragma unroll
        for (int j4 = 0; j4 < 16; j4++) {
            const float p0 = __expf(s4[j4].x - mnew);
            const float p1 = __expf(s4[j4].y - mnew);
            const float p2 = __expf(s4[j4].z - mnew);
            const float p3 = __expf(s4[j4].w - mnew);
            lsum += (p0 + p1) + (p2 + p3);
            const float4* v0 = Vs + (j4*4+0)*16;
            const float4* v1 = Vs + (j4*4+1)*16;
            const float4* v2 = Vs + (j4*4+2)*16;
            const float4* v3 = Vs + (j4*4+3)*16;
#pragma unroll
            for (int d4 = 0; d4 < 16; d4++) {
                float4 o = O[d4];
                float4 a = v0[d4], b = v1[d4], c = v2[d4], d = v3[d4];
                o.x += p0*a.x + p1*b.x + p2*c.x + p3*d.x;
                o.y += p0*a.y + p1*b.y + p2*c.y + p3*d.y;
                o.z += p0*a.z + p1*b.z + p2*c.z + p3*d.z;
                o.w += p0*a.w + p1*b.w + p2*c.w + p3*d.w;
                O[d4] = o;
            }
        }
        l += lsum;
        m = mnew;
    }

    // Normalize & write to g_att in [B,T,C] layout (col = h*64 + d)
    const float inv = 1.f / l;
    const int b = bh >> 4, h = bh & 15;
    float4* dst = (float4*)(g_att + ((size_t)(b*TSEQ + qg))*CDIM + h*DHEAD);
#pragma unroll
    for (int d4 = 0; d4 < 16; d4++) {
        float4 o = O[d4];
        o.x *= inv; o.y *= inv; o.z *= inv; o.w *= inv;
        dst[d4] = o;
    }
}

extern "C" void kernel_launch(void* const* d_in, const int* in_sizes, int n_in,
                              void* d_out, int out_size)
{
    (void)in_sizes; (void)n_in; (void)out_size;
    const float* x     = (const float*)d_in[0];
    const float* w_qkv = (const float*)d_in[1];
    const float* b_qkv = (const float*)d_in[2];
    const float* w_out = (const float*)d_in[3];
    const float* b_out = (const float*)d_in[4];
    float* out = (float*)d_out;

    // 1) QKV projection + bias + head-split transpose
    sgemm_kernel<<<dim3(3072/64, MROWS/64), 256>>>(x, w_qkv, b_qkv, nullptr, 3072, 1024, 0);
    // 2) Causal flash attention
    attn_kernel<<<dim3(TSEQ/64, BSZ*HH), 64>>>();
    // 3) Output projection + bias
    sgemm_kernel<<<dim3(1024/64, MROWS/64), 256>>>(nullptr, w_out, b_out, out, 1024, 1024, 1);
}

// round 3
// speedup vs baseline: 1.2517x; 1.2517x over previous
#include <cuda_runtime.h>
#include <cstdint>

#define BSZ  4
#define TSEQ 2048
#define CDIM 1024
#define HH   16
#define DHEAD 64
#define MROWS (BSZ*TSEQ)   // 8192
#define KDIM 1024

// ---------------- device scratch (allocation-free rule) ----------------
__device__ float g_q[(size_t)BSZ*HH*TSEQ*DHEAD];
__device__ float g_k[(size_t)BSZ*HH*TSEQ*DHEAD];
__device__ float g_v[(size_t)BSZ*HH*TSEQ*DHEAD];
__device__ float g_att[(size_t)MROWS*CDIM];

// ---------------- helpers ----------------
__device__ __forceinline__ uint32_t f2tf32(float f) {
    uint32_t r;
    asm("cvt.rna.tf32.f32 %0, %1;" : "=r"(r) : "f"(f));
    return r;
}

__device__ __forceinline__ void mma8(float* d, const uint32_t* a, const uint32_t* b) {
    asm("mma.sync.aligned.m16n8k8.row.col.f32.tf32.tf32.f32 "
        "{%0,%1,%2,%3}, {%4,%5,%6,%7}, {%8,%9}, {%0,%1,%2,%3};"
        : "+f"(d[0]), "+f"(d[1]), "+f"(d[2]), "+f"(d[3])
        : "r"(a[0]), "r"(a[1]), "r"(a[2]), "r"(a[3]), "r"(b[0]), "r"(b[1]));
}

// ---------------- tf32 mma.sync GEMM ----------------
// C[M,N] = A[M,1024] @ B[1024,N] + bias
// CTA tile 128x128, BK=32, 256 threads = 8 warps (2m x 4n), warp tile 64x32.
// mode 0: A = x, scatter to g_q/g_k/g_v ([B,H,T,Dh]) with bias
// mode 1: A = g_att -> Cout with bias
#define BK 32
#define AS_STR 36                       // 32 + 4 pad (conflict-free frag LDS)
#define AS_FLOATS (128*AS_STR)          // 4608
#define BS_FLOATS (BK*128)              // 4096
#define MM_SMEM ((2*AS_FLOATS + 2*BS_FLOATS)*4)   // 69632 B

__global__ __launch_bounds__(256)
void mm_kernel(const float* __restrict__ A, const float* __restrict__ Bw,
               const float* __restrict__ bias, float* __restrict__ Cout,
               int N, int mode)
{
    extern __shared__ float sm[];
    float* As[2] = { sm, sm + AS_FLOATS };
    float* Bs[2] = { sm + 2*AS_FLOATS, sm + 2*AS_FLOATS + BS_FLOATS };

    const int tid  = threadIdx.x;
    const int lane = tid & 31;
    const int warp = tid >> 5;
    const int wm = (warp >> 2) * 64;      // 0 or 64
    const int wn = (warp & 3) * 32;       // 0,32,64,96
    const int g  = lane >> 2;             // groupID 0..7
    const int ig = lane & 3;              // thread-in-group 0..3

    const int m0 = blockIdx.y * 128;
    const int n0 = blockIdx.x * 128;

    if (mode) A = g_att;

    float d[4][4][4];                     // [mt][nt][reg]
#pragma unroll
    for (int mt = 0; mt < 4; mt++)
#pragma unroll
        for (int nt = 0; nt < 4; nt++)
#pragma unroll
            for (int r = 0; r < 4; r++) d[mt][nt][r] = 0.f;

    float4 ra[4], rb[4];
    // A tile: 128 rows x 8 float4 (k), idx = tid + 256*i : m = idx>>3, k4 = idx&7
    // B tile: 32 rows (k) x 32 float4 (n), idx: k = idx>>5, n4 = idx&31

#define LDG(c) do {                                                              \
    _Pragma("unroll") for (int i = 0; i < 4; i++) {                              \
        int idx = tid + 256*i;                                                   \
        ra[i] = *(const float4*)(A + (size_t)(m0 + (idx>>3))*KDIM + (c)*BK + (idx&7)*4); } \
    _Pragma("unroll") for (int i = 0; i < 4; i++) {                              \
        int idx = tid + 256*i;                                                   \
        rb[i] = *(const float4*)(Bw + (size_t)((c)*BK + (idx>>5))*N + n0 + (idx&31)*4); } \
} while (0)

#define STS(p) do {                                                              \
    _Pragma("unroll") for (int i = 0; i < 4; i++) {                              \
        int idx = tid + 256*i;                                                   \
        *(float4*)(As[p] + (idx>>3)*AS_STR + (idx&7)*4) = ra[i]; }               \
    _Pragma("unroll") for (int i = 0; i < 4; i++) {                              \
        int idx = tid + 256*i;                                                   \
        int k = idx >> 5, n4 = idx & 31;                                         \
        *(float4*)(Bs[p] + k*128 + ((n4*4) ^ ((k&3)<<3))) = rb[i]; }             \
} while (0)

#define COMPUTE(p) do {                                                          \
    const float* Ap = As[p];                                                     \
    const float* Bp = Bs[p];                                                     \
    _Pragma("unroll") for (int s = 0; s < 4; s++) {                              \
        const int k0 = s*8;                                                      \
        uint32_t af[4][4], bf[4][2];                                             \
        _Pragma("unroll") for (int mt = 0; mt < 4; mt++) {                       \
            const int r = wm + mt*16 + g;                                        \
            af[mt][0] = f2tf32(Ap[r*AS_STR + k0 + ig]);                          \
            af[mt][1] = f2tf32(Ap[(r+8)*AS_STR + k0 + ig]);                      \
            af[mt][2] = f2tf32(Ap[r*AS_STR + k0 + ig + 4]);                      \
            af[mt][3] = f2tf32(Ap[(r+8)*AS_STR + k0 + ig + 4]);                  \
        }                                                                        \
        _Pragma("unroll") for (int nt = 0; nt < 4; nt++) {                       \
            const int nn = wn + nt*8 + g;                                        \
            const int sw = ig << 3;                                              \
            bf[nt][0] = f2tf32(Bp[(k0+ig)*128 + (nn ^ sw)]);                     \
            bf[nt][1] = f2tf32(Bp[(k0+4+ig)*128 + (nn ^ sw)]);                   \
        }                                                                        \
        _Pragma("unroll") for (int mt = 0; mt < 4; mt++)                         \
            _Pragma("unroll") for (int nt = 0; nt < 4; nt++)                     \
                mma8(d[mt][nt], af[mt], bf[nt]);                                 \
    }                                                                            \
} while (0)

    LDG(0);
    STS(0);
    __syncthreads();
    for (int c = 1; c < KDIM/BK; c++) {
        LDG(c);
        COMPUTE((c+1)&1);
        STS(c&1);
        __syncthreads();
    }
    COMPUTE((KDIM/BK-1)&1);

    // ---- epilogue: bias + store (float2 per c-pair; 4-lane 32B contiguous = full sectors)
#pragma unroll
    for (int mt = 0; mt < 4; mt++) {
        const int r0 = m0 + wm + mt*16 + g;
#pragma unroll
        for (int nt = 0; nt < 4; nt++) {
            const int c0 = n0 + wn + nt*8 + ig*2;
            const float b0 = bias[c0], b1 = bias[c0+1];
            if (mode == 0) {
                const int sec = c0 >> 10;
                const int h   = (c0 & 1023) >> 6;
                const int dd  = c0 & 63;
                float* dstp = (sec == 0) ? g_q : ((sec == 1) ? g_k : g_v);
#pragma unroll
                for (int rr = 0; rr < 2; rr++) {
                    const int r = r0 + rr*8;
                    const int b = r >> 11, t = r & 2047;
                    float2 v = make_float2(d[mt][nt][rr*2+0] + b0, d[mt][nt][rr*2+1] + b1);
                    *(float2*)(dstp + (((size_t)(b*HH + h))*TSEQ + t)*DHEAD + dd) = v;
                }
            } else {
#pragma unroll
                for (int rr = 0; rr < 2; rr++) {
                    const int r = r0 + rr*8;
                    float2 v = make_float2(d[mt][nt][rr*2+0] + b0, d[mt][nt][rr*2+1] + b1);
                    *(float2*)(Cout + (size_t)r*N + c0) = v;
                }
            }
        }
    }
}

// ---------------- fp32 flash attention (unchanged) ----------------
__global__ __launch_bounds__(64)
void attn_kernel()
{
    __shared__ float  Qs[64*64];
    __shared__ float  Ks[64*64];
    __shared__ float4 Vs[64*16];

    const int tid = threadIdx.x;
    const int bh  = blockIdx.y;
    const int qt  = (gridDim.x - 1) - blockIdx.x;
    const int q0  = qt * 64;

    const float* Qg = g_q + (size_t)bh * TSEQ * DHEAD;
    const float* Kg = g_k + (size_t)bh * TSEQ * DHEAD;
    const float* Vg = g_v + (size_t)bh * TSEQ * DHEAD;

    for (int f = tid; f < 1024; f += 64) {
        const int i = f >> 4, d4 = f & 15;
        float4 v = *(const float4*)(Qg + (size_t)(q0 + i)*DHEAD + d4*4);
        const int db = d4*4, sw = db & 28, ix = i ^ sw;
        Qs[(db+0)*64 + ix] = v.x * 0.125f;
        Qs[(db+1)*64 + ix] = v.y * 0.125f;
        Qs[(db+2)*64 + ix] = v.z * 0.125f;
        Qs[(db+3)*64 + ix] = v.w * 0.125f;
    }

    float m = -1e30f, l = 0.f;
    float4 O[16];
#pragma unroll
    for (int d4 = 0; d4 < 16; d4++) O[d4] = make_float4(0.f, 0.f, 0.f, 0.f);

    const int qg = q0 + tid;

    for (int jt = 0; jt <= qt; jt++) {
        const int j0 = jt * 64;
        __syncthreads();
        for (int f = tid; f < 1024; f += 64) {
            const int j = f >> 4, d4 = f & 15;
            float4 kv = *(const float4*)(Kg + (size_t)(j0 + j)*DHEAD + d4*4);
            const int db = d4*4, sw = db & 28, jx = j ^ sw;
            Ks[(db+0)*64 + jx] = kv.x;
            Ks[(db+1)*64 + jx] = kv.y;
            Ks[(db+2)*64 + jx] = kv.z;
            Ks[(db+3)*64 + jx] = kv.w;
            Vs[j*16 + d4] = *(const float4*)(Vg + (size_t)(j0 + j)*DHEAD + d4*4);
        }
        __syncthreads();

        float4 s4[16];
#pragma unroll
        for (int j4 = 0; j4 < 16; j4++) s4[j4] = make_float4(0.f, 0.f, 0.f, 0.f);

#pragma unroll 4
        for (int d = 0; d < 64; d++) {
            const float qd = Qs[d*64 + (tid ^ (d & 28))];
            const float4* kr = (const float4*)Ks + d*16;
            const int sw4 = (d & 28) >> 2;
#pragma unroll
            for (int j4 = 0; j4 < 16; j4++) {
                float4 kk = kr[j4 ^ sw4];
                s4[j4].x += qd * kk.x;
                s4[j4].y += qd * kk.y;
                s4[j4].z += qd * kk.z;
                s4[j4].w += qd * kk.w;
            }
        }

        if (jt == qt) {
#pragma unroll
            for (int j4 = 0; j4 < 16; j4++) {
                const int jb = j0 + j4*4;
                if (jb + 0 > qg) s4[j4].x = -1e30f;
                if (jb + 1 > qg) s4[j4].y = -1e30f;
                if (jb + 2 > qg) s4[j4].z = -1e30f;
                if (jb + 3 > qg) s4[j4].w = -1e30f;
            }
        }

        float mnew = m;
#pragma unroll
        for (int j4 = 0; j4 < 16; j4++)
            mnew = fmaxf(mnew, fmaxf(fmaxf(s4[j4].x, s4[j4].y), fmaxf(s4[j4].z, s4[j4].w)));
        const float corr = __expf(m - mnew);
        l *= corr;
#pragma unroll
        for (int d4 = 0; d4 < 16; d4++) {
            O[d4].x *= corr; O[d4].y *= corr; O[d4].z *= corr; O[d4].w *= corr;
        }

        float lsum = 0.f;
#pragma unroll
        for (int j4 = 0; j4 < 16; j4++) {
            const float p0 = __expf(s4[j4].x - mnew);
            const float p1 = __expf(s4[j4].y - mnew);
            const float p2 = __expf(s4[j4].z - mnew);
            const float p3 = __expf(s4[j4].w - mnew);
            lsum += (p0 + p1) + (p2 + p3);
            const float4* v0 = Vs + (j4*4+0)*16;
            const float4* v1 = Vs + (j4*4+1)*16;
            const float4* v2 = Vs + (j4*4+2)*16;
            const float4* v3 = Vs + (j4*4+3)*16;
#pragma unroll
            for (int d4 = 0; d4 < 16; d4++) {
                float4 o = O[d4];
                float4 a = v0[d4], b = v1[d4], c = v2[d4], dv = v3[d4];
                o.x += p0*a.x + p1*b.x + p2*c.x + p3*dv.x;
                o.y += p0*a.y + p1*b.y + p2*c.y + p3*dv.y;
                o.z += p0*a.z + p1*b.z + p2*c.z + p3*dv.z;
                o.w += p0*a.w + p1*b.w + p2*c.w + p3*dv.w;
                O[d4] = o;
            }
        }
        l += lsum;
        m = mnew;
    }

    const float inv = 1.f / l;
    const int b = bh >> 4, h = bh & 15;
    float4* dst = (float4*)(g_att + ((size_t)(b*TSEQ + qg))*CDIM + h*DHEAD);
#pragma unroll
    for (int d4 = 0; d4 < 16; d4++) {
        float4 o = O[d4];
        o.x *= inv; o.y *= inv; o.z *= inv; o.w *= inv;
        dst[d4] = o;
    }
}

// ---------------- launch ----------------
extern "C" void kernel_launch(void* const* d_in, const int* in_sizes, int n_in,
                              void* d_out, int out_size)
{
    (void)in_sizes; (void)n_in; (void)out_size;
    const float* x     = (const float*)d_in[0];
    const float* w_qkv = (const float*)d_in[1];
    const float* b_qkv = (const float*)d_in[2];
    const float* w_out = (const float*)d_in[3];
    const float* b_out = (const float*)d_in[4];
    float* out = (float*)d_out;

    static int smem_set = 0;
    if (!smem_set) {
        cudaFuncSetAttribute(mm_kernel, cudaFuncAttributeMaxDynamicSharedMemorySize, MM_SMEM);
        smem_set = 1;
    }

    // 1) QKV projection (mma.sync tf32) + bias + head-split scatter
    mm_kernel<<<dim3(3072/128, MROWS/128), 256, MM_SMEM>>>(x, w_qkv, b_qkv, nullptr, 3072, 0);
    // 2) causal flash attention (fp32 scalar)
    attn_kernel<<<dim3(TSEQ/64, BSZ*HH), 64>>>();
    // 3) output projection (mma.sync tf32) + bias
    mm_kernel<<<dim3(1024/128, MROWS/128), 256, MM_SMEM>>>(nullptr, w_out, b_out, out, 1024, 1);
}

// round 4
// speedup vs baseline: 2.3442x; 1.8728x over previous
#include <cuda_runtime.h>
#include <cstdint>

#define BSZ  4
#define TSEQ 2048
#define CDIM 1024
#define HH   16
#define DHEAD 64
#define MROWS (BSZ*TSEQ)   // 8192
#define KDIM 1024

// ---------------- device scratch (allocation-free rule) ----------------
__device__ float g_q[(size_t)BSZ*HH*TSEQ*DHEAD];
__device__ float g_k[(size_t)BSZ*HH*TSEQ*DHEAD];
__device__ float g_v[(size_t)BSZ*HH*TSEQ*DHEAD];
__device__ float g_att[(size_t)MROWS*CDIM];

// ---------------- helpers ----------------
__device__ __forceinline__ uint32_t f2tf32(float f) {
    uint32_t r;
    asm("cvt.rna.tf32.f32 %0, %1;" : "=r"(r) : "f"(f));
    return r;
}

__device__ __forceinline__ void mma8(float* d, const uint32_t* a, const uint32_t* b) {
    asm("mma.sync.aligned.m16n8k8.row.col.f32.tf32.tf32.f32 "
        "{%0,%1,%2,%3}, {%4,%5,%6,%7}, {%8,%9}, {%0,%1,%2,%3};"
        : "+f"(d[0]), "+f"(d[1]), "+f"(d[2]), "+f"(d[3])
        : "r"(a[0]), "r"(a[1]), "r"(a[2]), "r"(a[3]), "r"(b[0]), "r"(b[1]));
}

// ---------------- tf32 mma.sync GEMM ----------------
// C[M,N] = A[M,1024] @ B[1024,N] + bias, CTA tile 128x128, BK=32, 8 warps.
// smem holds PRE-CONVERTED tf32 bits (cvt done at STS time, not in MMA loop).
#define BK 32
#define AS_STR 36
#define AS_WORDS (128*AS_STR)
#define BS_WORDS (BK*128)
#define MM_SMEM ((2*AS_WORDS + 2*BS_WORDS)*4)

__global__ __launch_bounds__(256)
void mm_kernel(const float* __restrict__ A, const float* __restrict__ Bw,
               const float* __restrict__ bias, float* __restrict__ Cout,
               int N, int mode)
{
    extern __shared__ uint32_t sm[];
    uint32_t* As[2] = { sm, sm + AS_WORDS };
    uint32_t* Bs[2] = { sm + 2*AS_WORDS, sm + 2*AS_WORDS + BS_WORDS };

    const int tid  = threadIdx.x;
    const int lane = tid & 31;
    const int warp = tid >> 5;
    const int wm = (warp >> 2) * 64;
    const int wn = (warp & 3) * 32;
    const int g  = lane >> 2;
    const int ig = lane & 3;

    const int m0 = blockIdx.y * 128;
    const int n0 = blockIdx.x * 128;

    if (mode) A = g_att;

    float d[4][4][4];
#pragma unroll
    for (int mt = 0; mt < 4; mt++)
#pragma unroll
        for (int nt = 0; nt < 4; nt++)
#pragma unroll
            for (int r = 0; r < 4; r++) d[mt][nt][r] = 0.f;

    float4 ra[4], rb[4];

#define LDG(c) do {                                                              \
    _Pragma("unroll") for (int i = 0; i < 4; i++) {                              \
        int idx = tid + 256*i;                                                   \
        ra[i] = *(const float4*)(A + (size_t)(m0 + (idx>>3))*KDIM + (c)*BK + (idx&7)*4); } \
    _Pragma("unroll") for (int i = 0; i < 4; i++) {                              \
        int idx = tid + 256*i;                                                   \
        rb[i] = *(const float4*)(Bw + (size_t)((c)*BK + (idx>>5))*N + n0 + (idx&31)*4); } \
} while (0)

#define STS(p) do {                                                              \
    _Pragma("unroll") for (int i = 0; i < 4; i++) {                              \
        int idx = tid + 256*i;                                                   \
        uint4 t = make_uint4(f2tf32(ra[i].x), f2tf32(ra[i].y), f2tf32(ra[i].z), f2tf32(ra[i].w)); \
        *(uint4*)(As[p] + (idx>>3)*AS_STR + (idx&7)*4) = t; }                    \
    _Pragma("unroll") for (int i = 0; i < 4; i++) {                              \
        int idx = tid + 256*i;                                                   \
        int k = idx >> 5, n4 = idx & 31;                                         \
        uint4 t = make_uint4(f2tf32(rb[i].x), f2tf32(rb[i].y), f2tf32(rb[i].z), f2tf32(rb[i].w)); \
        *(uint4*)(Bs[p] + k*128 + ((n4*4) ^ ((k&3)<<3))) = t; }                  \
} while (0)

#define COMPUTE(p) do {                                                          \
    const uint32_t* Ap = As[p];                                                  \
    const uint32_t* Bp = Bs[p];                                                  \
    _Pragma("unroll") for (int s = 0; s < 4; s++) {                              \
        const int k0 = s*8;                                                      \
        uint32_t af[4][4], bf[4][2];                                             \
        _Pragma("unroll") for (int mt = 0; mt < 4; mt++) {                       \
            const int r = wm + mt*16 + g;                                        \
            af[mt][0] = Ap[r*AS_STR + k0 + ig];                                  \
            af[mt][1] = Ap[(r+8)*AS_STR + k0 + ig];                              \
            af[mt][2] = Ap[r*AS_STR + k0 + ig + 4];                              \
            af[mt][3] = Ap[(r+8)*AS_STR + k0 + ig + 4];                          \
        }                                                                        \
        _Pragma("unroll") for (int nt = 0; nt < 4; nt++) {                       \
            const int nn = wn + nt*8 + g;                                        \
            const int sw = ig << 3;                                              \
            bf[nt][0] = Bp[(k0+ig)*128 + (nn ^ sw)];                             \
            bf[nt][1] = Bp[(k0+4+ig)*128 + (nn ^ sw)];                           \
        }                                                                        \
        _Pragma("unroll") for (int mt = 0; mt < 4; mt++)                         \
            _Pragma("unroll") for (int nt = 0; nt < 4; nt++)                     \
                mma8(d[mt][nt], af[mt], bf[nt]);                                 \
    }                                                                            \
} while (0)

    LDG(0);
    STS(0);
    __syncthreads();
    for (int c = 1; c < KDIM/BK; c++) {
        LDG(c);
        COMPUTE((c+1)&1);
        STS(c&1);
        __syncthreads();
    }
    COMPUTE((KDIM/BK-1)&1);

#pragma unroll
    for (int mt = 0; mt < 4; mt++) {
        const int r0 = m0 + wm + mt*16 + g;
#pragma unroll
        for (int nt = 0; nt < 4; nt++) {
            const int c0 = n0 + wn + nt*8 + ig*2;
            const float b0 = bias[c0], b1 = bias[c0+1];
            if (mode == 0) {
                const int sec = c0 >> 10;
                const int h   = (c0 & 1023) >> 6;
                const int dd  = c0 & 63;
                float* dstp = (sec == 0) ? g_q : ((sec == 1) ? g_k : g_v);
#pragma unroll
                for (int rr = 0; rr < 2; rr++) {
                    const int r = r0 + rr*8;
                    const int b = r >> 11, t = r & 2047;
                    float2 v = make_float2(d[mt][nt][rr*2+0] + b0, d[mt][nt][rr*2+1] + b1);
                    *(float2*)(dstp + (((size_t)(b*HH + h))*TSEQ + t)*DHEAD + dd) = v;
                }
            } else {
#pragma unroll
                for (int rr = 0; rr < 2; rr++) {
                    const int r = r0 + rr*8;
                    float2 v = make_float2(d[mt][nt][rr*2+0] + b0, d[mt][nt][rr*2+1] + b1);
                    *(float2*)(Cout + (size_t)r*N + c0) = v;
                }
            }
        }
    }
}

// ---------------- tensor-core flash attention (tf32 mma.sync) ----------------
// BM=64 (4 warps x 16 rows), BN=64, Dh=64. 128 threads.
// smem: Q/K/V/P tiles 64 x 76 (pad) of tf32 bits. All fragment access patterns
// verified conflict-free (bank shift 12 per row).
#define AT_STR 76
#define AT_SMEM (4*64*AT_STR*4)   // 77824 B

__global__ __launch_bounds__(128)
void attn_kernel()
{
    extern __shared__ uint32_t smu[];
    uint32_t* Qs = smu;
    uint32_t* Ks = Qs + 64*AT_STR;
    uint32_t* Vs = Ks + 64*AT_STR;
    uint32_t* Ps = Vs + 64*AT_STR;

    const int tid  = threadIdx.x;
    const int lane = tid & 31;
    const int w    = tid >> 5;
    const int g    = lane >> 2;
    const int ig   = lane & 3;
    const int bh = blockIdx.y;
    const int qt = (gridDim.x - 1) - blockIdx.x;   // long blocks first
    const int q0 = qt * 64;

    const float* Qg = g_q + (size_t)bh * TSEQ * DHEAD;
    const float* Kg = g_k + (size_t)bh * TSEQ * DHEAD;
    const float* Vg = g_v + (size_t)bh * TSEQ * DHEAD;

    // Load Q tile once, scaled, converted to tf32
#pragma unroll
    for (int i = 0; i < 8; i++) {
        const int f = tid + 128*i;            // 0..1023
        const int row = f >> 4, c4 = f & 15;
        float4 v = *(const float4*)(Qg + (size_t)(q0+row)*DHEAD + c4*4);
        uint4 t = make_uint4(f2tf32(v.x*0.125f), f2tf32(v.y*0.125f),
                             f2tf32(v.z*0.125f), f2tf32(v.w*0.125f));
        *(uint4*)(Qs + row*AT_STR + c4*4) = t;
    }

    const int r0 = 16*w + g;                  // this thread's row pair: r0, r0+8
    float O[8][4];
#pragma unroll
    for (int nt = 0; nt < 8; nt++)
#pragma unroll
        for (int r = 0; r < 4; r++) O[nt][r] = 0.f;
    float m0 = -1e30f, m1 = -1e30f, l0 = 0.f, l1 = 0.f;

    for (int jt = 0; jt <= qt; jt++) {
        const int j0 = jt * 64;
        __syncthreads();
#pragma unroll
        for (int i = 0; i < 8; i++) {
            const int f = tid + 128*i;
            const int row = f >> 4, c4 = f & 15;
            float4 kv = *(const float4*)(Kg + (size_t)(j0+row)*DHEAD + c4*4);
            float4 vv = *(const float4*)(Vg + (size_t)(j0+row)*DHEAD + c4*4);
            *(uint4*)(Ks + row*AT_STR + c4*4) =
                make_uint4(f2tf32(kv.x), f2tf32(kv.y), f2tf32(kv.z), f2tf32(kv.w));
            *(uint4*)(Vs + row*AT_STR + c4*4) =
                make_uint4(f2tf32(vv.x), f2tf32(vv.y), f2tf32(vv.z), f2tf32(vv.w));
        }
        __syncthreads();

        // S = Q K^T  (16x64 per warp)
        float s[8][4];
#pragma unroll
        for (int nt = 0; nt < 8; nt++)
#pragma unroll
            for (int r = 0; r < 4; r++) s[nt][r] = 0.f;

#pragma unroll
        for (int k0 = 0; k0 < 64; k0 += 8) {
            uint32_t a[4];
            a[0] = Qs[r0*AT_STR + k0 + ig];
            a[1] = Qs[(r0+8)*AT_STR + k0 + ig];
            a[2] = Qs[r0*AT_STR + k0 + ig + 4];
            a[3] = Qs[(r0+8)*AT_STR + k0 + ig + 4];
#pragma unroll
            for (int nt = 0; nt < 8; nt++) {
                uint32_t b[2];
                b[0] = Ks[(nt*8+g)*AT_STR + k0 + ig];
                b[1] = Ks[(nt*8+g)*AT_STR + k0 + ig + 4];
                mma8(s[nt], a, b);
            }
        }

        // causal mask on diagonal tile
        if (jt == qt) {
            const int qa = q0 + r0, qb = qa + 8;
#pragma unroll
            for (int nt = 0; nt < 8; nt++) {
                const int j = j0 + nt*8 + 2*ig;
                if (j     > qa) s[nt][0] = -1e30f;
                if (j + 1 > qa) s[nt][1] = -1e30f;
                if (j     > qb) s[nt][2] = -1e30f;
                if (j + 1 > qb) s[nt][3] = -1e30f;
            }
        }

        // online softmax (rows r0, r0+8)
        float a0 = -1e30f, a1 = -1e30f;
#pragma unroll
        for (int nt = 0; nt < 8; nt++) {
            a0 = fmaxf(a0, fmaxf(s[nt][0], s[nt][1]));
            a1 = fmaxf(a1, fmaxf(s[nt][2], s[nt][3]));
        }
        a0 = fmaxf(a0, __shfl_xor_sync(0xFFFFFFFFu, a0, 1));
        a0 = fmaxf(a0, __shfl_xor_sync(0xFFFFFFFFu, a0, 2));
        a1 = fmaxf(a1, __shfl_xor_sync(0xFFFFFFFFu, a1, 1));
        a1 = fmaxf(a1, __shfl_xor_sync(0xFFFFFFFFu, a1, 2));

        const float mn0 = fmaxf(m0, a0), mn1 = fmaxf(m1, a1);
        const float c0 = __expf(m0 - mn0), c1 = __expf(m1 - mn1);
        l0 *= c0; l1 *= c1;
#pragma unroll
        for (int nt = 0; nt < 8; nt++) {
            O[nt][0] *= c0; O[nt][1] *= c0;
            O[nt][2] *= c1; O[nt][3] *= c1;
        }

        float t0 = 0.f, t1 = 0.f;
#pragma unroll
        for (int nt = 0; nt < 8; nt++) {
            const float p0 = __expf(s[nt][0] - mn0);
            const float p1 = __expf(s[nt][1] - mn0);
            const float p2 = __expf(s[nt][2] - mn1);
            const float p3 = __expf(s[nt][3] - mn1);
            t0 += p0 + p1; t1 += p2 + p3;
            *(uint2*)(Ps + r0*AT_STR + nt*8 + 2*ig)     = make_uint2(f2tf32(p0), f2tf32(p1));
            *(uint2*)(Ps + (r0+8)*AT_STR + nt*8 + 2*ig) = make_uint2(f2tf32(p2), f2tf32(p3));
        }
        t0 += __shfl_xor_sync(0xFFFFFFFFu, t0, 1);
        t0 += __shfl_xor_sync(0xFFFFFFFFu, t0, 2);
        t1 += __shfl_xor_sync(0xFFFFFFFFu, t1, 1);
        t1 += __shfl_xor_sync(0xFFFFFFFFu, t1, 2);
        l0 += t0; l1 += t1;
        m0 = mn0; m1 = mn1;
        __syncwarp();

        // O += P @ V  (per-warp P region; no block sync needed)
#pragma unroll
        for (int k0 = 0; k0 < 64; k0 += 8) {
            uint32_t a[4];
            a[0] = Ps[r0*AT_STR + k0 + ig];
            a[1] = Ps[(r0+8)*AT_STR + k0 + ig];
            a[2] = Ps[r0*AT_STR + k0 + ig + 4];
            a[3] = Ps[(r0+8)*AT_STR + k0 + ig + 4];
#pragma unroll
            for (int nt = 0; nt < 8; nt++) {
                uint32_t b[2];
                b[0] = Vs[(k0+ig)*AT_STR + nt*8 + g];
                b[1] = Vs[(k0+ig+4)*AT_STR + nt*8 + g];
                mma8(O[nt], a, b);
            }
        }
        __syncwarp();
    }

    // normalize, store to g_att [B,T,C] (col = h*64 + d)
    const float inv0 = 1.f / l0, inv1 = 1.f / l1;
    const int b = bh >> 4, h = bh & 15;
    float* base = g_att + ((size_t)(b*TSEQ + q0 + r0))*CDIM + h*DHEAD;
#pragma unroll
    for (int nt = 0; nt < 8; nt++) {
        *(float2*)(base + nt*8 + 2*ig) =
            make_float2(O[nt][0]*inv0, O[nt][1]*inv0);
        *(float2*)(base + (size_t)8*CDIM + nt*8 + 2*ig) =
            make_float2(O[nt][2]*inv1, O[nt][3]*inv1);
    }
}

// ---------------- launch ----------------
extern "C" void kernel_launch(void* const* d_in, const int* in_sizes, int n_in,
                              void* d_out, int out_size)
{
    (void)in_sizes; (void)n_in; (void)out_size;
    const float* x     = (const float*)d_in[0];
    const float* w_qkv = (const float*)d_in[1];
    const float* b_qkv = (const float*)d_in[2];
    const float* w_out = (const float*)d_in[3];
    const float* b_out = (const float*)d_in[4];
    float* out = (float*)d_out;

    cudaFuncSetAttribute(mm_kernel,   cudaFuncAttributeMaxDynamicSharedMemorySize, MM_SMEM);
    cudaFuncSetAttribute(attn_kernel, cudaFuncAttributeMaxDynamicSharedMemorySize, AT_SMEM);

    // 1) QKV projection (mma.sync tf32) + bias + head-split scatter
    mm_kernel<<<dim3(3072/128, MROWS/128), 256, MM_SMEM>>>(x, w_qkv, b_qkv, nullptr, 3072, 0);
    // 2) causal flash attention (mma.sync tf32)
    attn_kernel<<<dim3(TSEQ/64, BSZ*HH), 128, AT_SMEM>>>();
    // 3) output projection (mma.sync tf32) + bias
    mm_kernel<<<dim3(1024/128, MROWS/128), 256, MM_SMEM>>>(nullptr, w_out, b_out, out, 1024, 1);
}

// round 5
// speedup vs baseline: 3.4730x; 1.4816x over previous
#include <cuda_runtime.h>
#include <cstdint>

#define BSZ  4
#define TSEQ 2048
#define CDIM 1024
#define HH   16
#define DHEAD 64
#define MROWS (BSZ*TSEQ)   // 8192
#define KDIM 1024

// ---------------- device scratch (allocation-free rule) ----------------
__device__ __align__(16) float g_q[(size_t)BSZ*HH*TSEQ*DHEAD];
__device__ __align__(16) float g_k[(size_t)BSZ*HH*TSEQ*DHEAD];
__device__ __align__(16) float g_v[(size_t)BSZ*HH*TSEQ*DHEAD];
__device__ __align__(16) float g_att[(size_t)MROWS*CDIM];

// ---------------- helpers ----------------
__device__ __forceinline__ uint32_t f2tf32(float f) {
    uint32_t r;
    asm("cvt.rna.tf32.f32 %0, %1;" : "=r"(r) : "f"(f));
    return r;
}

__device__ __forceinline__ void mma8(float* d, const uint32_t* a, const uint32_t* b) {
    asm("mma.sync.aligned.m16n8k8.row.col.f32.tf32.tf32.f32 "
        "{%0,%1,%2,%3}, {%4,%5,%6,%7}, {%8,%9}, {%0,%1,%2,%3};"
        : "+f"(d[0]), "+f"(d[1]), "+f"(d[2]), "+f"(d[3])
        : "r"(a[0]), "r"(a[1]), "r"(a[2]), "r"(a[3]), "r"(b[0]), "r"(b[1]));
}

__device__ __forceinline__ uint32_t smem_u32(const void* p) {
    uint32_t a;
    asm("{ .reg .u64 t; cvta.to.shared.u64 t, %1; cvt.u32.u64 %0, t; }" : "=r"(a) : "l"(p));
    return a;
}

__device__ __forceinline__ void cp16(uint32_t s, const void* g) {
    asm volatile("cp.async.cg.shared.global [%0], [%1], 16;" :: "r"(s), "l"(g));
}
#define CP_COMMIT() asm volatile("cp.async.commit_group;" ::: "memory")
#define CP_WAIT1()  asm volatile("cp.async.wait_group 1;" ::: "memory")

// ---------------- tf32 mma.sync GEMM, cp.async 3-stage ----------------
// C[M,N] = A[M,1024] @ B[1024,N] + bias, CTA tile 128x128, BK=32, 8 warps, 2 CTA/SM.
#define BK 32
#define AS_STR 36
#define A_WORDS (128*AS_STR)            // 4608
#define B_WORDS (BK*128)                // 4096
#define ST_WORDS (A_WORDS + B_WORDS)    // 8704
#define STAGES 3
#define MM_SMEM (STAGES*ST_WORDS*4)     // 104448 B

__global__ __launch_bounds__(256, 2)
void mm_kernel(const float* __restrict__ A, const float* __restrict__ Bw,
               const float* __restrict__ bias, float* __restrict__ Cout,
               int N, int mode)
{
    extern __shared__ float sm[];
    const uint32_t sb = smem_u32(sm);

    const int tid  = threadIdx.x;
    const int lane = tid & 31;
    const int warp = tid >> 5;
    const int wm = (warp >> 2) * 64;
    const int wn = (warp & 3) * 32;
    const int g  = lane >> 2;
    const int ig = lane & 3;

    const int m0 = blockIdx.y * 128;
    const int n0 = blockIdx.x * 128;

    if (mode) A = g_att;

    float d[4][4][4];
#pragma unroll
    for (int mt = 0; mt < 4; mt++)
#pragma unroll
        for (int nt = 0; nt < 4; nt++)
#pragma unroll
            for (int r = 0; r < 4; r++) d[mt][nt][r] = 0.f;

#define LDG_ASYNC(c, st) do {                                                     \
    uint32_t _sa = sb + (st)*ST_WORDS*4;                                          \
    uint32_t _sbB = _sa + A_WORDS*4;                                              \
    _Pragma("unroll") for (int i = 0; i < 4; i++) {                               \
        int idx = tid + 256*i; int row = idx >> 3, k4 = idx & 7;                  \
        cp16(_sa + (row*AS_STR + k4*4)*4,                                         \
             A + (size_t)(m0 + row)*KDIM + (c)*BK + k4*4); }                      \
    _Pragma("unroll") for (int i = 0; i < 4; i++) {                               \
        int idx = tid + 256*i; int k = idx >> 5, n4 = idx & 31;                   \
        cp16(_sbB + (k*128 + ((n4*4) ^ ((k&3)<<3)))*4,                            \
             Bw + (size_t)((c)*BK + k)*N + n0 + n4*4); }                          \
} while (0)

#define COMPUTE(st) do {                                                          \
    const float* Ap = sm + (st)*ST_WORDS;                                         \
    const float* Bp = Ap + A_WORDS;                                               \
    _Pragma("unroll") for (int s = 0; s < 4; s++) {                               \
        const int k0 = s*8;                                                       \
        uint32_t af[4][4], bf[4][2];                                              \
        _Pragma("unroll") for (int mt = 0; mt < 4; mt++) {                        \
            const int r = wm + mt*16 + g;                                         \
            af[mt][0] = f2tf32(Ap[r*AS_STR + k0 + ig]);                           \
            af[mt][1] = f2tf32(Ap[(r+8)*AS_STR + k0 + ig]);                       \
            af[mt][2] = f2tf32(Ap[r*AS_STR + k0 + ig + 4]);                       \
            af[mt][3] = f2tf32(Ap[(r+8)*AS_STR + k0 + ig + 4]);                   \
        }                                                                         \
        _Pragma("unroll") for (int nt = 0; nt < 4; nt++) {                        \
            const int nn = wn + nt*8 + g;                                         \
            const int sw = ig << 3;                                               \
            bf[nt][0] = f2tf32(Bp[(k0+ig)*128 + (nn ^ sw)]);                      \
            bf[nt][1] = f2tf32(Bp[(k0+4+ig)*128 + (nn ^ sw)]);                    \
        }                                                                         \
        _Pragma("unroll") for (int mt = 0; mt < 4; mt++)                          \
            _Pragma("unroll") for (int nt = 0; nt < 4; nt++)                      \
                mma8(d[mt][nt], af[mt], bf[nt]);                                  \
    }                                                                             \
} while (0)

    LDG_ASYNC(0, 0); CP_COMMIT();
    LDG_ASYNC(1, 1); CP_COMMIT();

#pragma unroll 1
    for (int c = 0; c < KDIM/BK; c++) {
        CP_WAIT1();
        __syncthreads();
        if (c + 2 < KDIM/BK) {
            const int st = (c + 2) % STAGES;
            LDG_ASYNC(c + 2, st);
        }
        CP_COMMIT();
        COMPUTE(c % STAGES);
    }

    // ---- epilogue: bias + store
#pragma unroll
    for (int mt = 0; mt < 4; mt++) {
        const int r0 = m0 + wm + mt*16 + g;
#pragma unroll
        for (int nt = 0; nt < 4; nt++) {
            const int c0 = n0 + wn + nt*8 + ig*2;
            const float b0 = bias[c0], b1 = bias[c0+1];
            if (mode == 0) {
                const int sec = c0 >> 10;
                const int h   = (c0 & 1023) >> 6;
                const int dd  = c0 & 63;
                float* dstp = (sec == 0) ? g_q : ((sec == 1) ? g_k : g_v);
#pragma unroll
                for (int rr = 0; rr < 2; rr++) {
                    const int r = r0 + rr*8;
                    const int b = r >> 11, t = r & 2047;
                    float2 v = make_float2(d[mt][nt][rr*2+0] + b0, d[mt][nt][rr*2+1] + b1);
                    *(float2*)(dstp + (((size_t)(b*HH + h))*TSEQ + t)*DHEAD + dd) = v;
                }
            } else {
#pragma unroll
                for (int rr = 0; rr < 2; rr++) {
                    const int r = r0 + rr*8;
                    float2 v = make_float2(d[mt][nt][rr*2+0] + b0, d[mt][nt][rr*2+1] + b1);
                    *(float2*)(Cout + (size_t)r*N + c0) = v;
                }
            }
        }
    }
}

// ---------------- tensor-core flash attention (tf32 mma.sync) ----------------
// BM=64 (4 warps x 16 rows), BN=64, Dh=64. 128 threads.
// Q/V/P: plain stride-76 rows (verified conflict-free for their access patterns).
// K: XOR-swizzled columns  k -> k ^ ((row&7)<<2)  (fixes 8-way conflict on S b-frags).
#define AT_STR 76
#define AT_SMEM (4*64*AT_STR*4)   // 77824 B

__global__ __launch_bounds__(128, 2)
void attn_kernel()
{
    extern __shared__ uint32_t smu[];
    uint32_t* Qs = smu;
    uint32_t* Ks = Qs + 64*AT_STR;
    uint32_t* Vs = Ks + 64*AT_STR;
    uint32_t* Ps = Vs + 64*AT_STR;

    const int tid  = threadIdx.x;
    const int lane = tid & 31;
    const int w    = tid >> 5;
    const int g    = lane >> 2;
    const int ig   = lane & 3;
    const int bh = blockIdx.y;
    const int qt = (gridDim.x - 1) - blockIdx.x;   // long blocks first
    const int q0 = qt * 64;

    const float* Qg = g_q + (size_t)bh * TSEQ * DHEAD;
    const float* Kg = g_k + (size_t)bh * TSEQ * DHEAD;
    const float* Vg = g_v + (size_t)bh * TSEQ * DHEAD;

#pragma unroll
    for (int i = 0; i < 8; i++) {
        const int f = tid + 128*i;
        const int row = f >> 4, c4 = f & 15;
        float4 v = *(const float4*)(Qg + (size_t)(q0+row)*DHEAD + c4*4);
        uint4 t = make_uint4(f2tf32(v.x*0.125f), f2tf32(v.y*0.125f),
                             f2tf32(v.z*0.125f), f2tf32(v.w*0.125f));
        *(uint4*)(Qs + row*AT_STR + c4*4) = t;
    }

    const int r0 = 16*w + g;
    float O[8][4];
#pragma unroll
    for (int nt = 0; nt < 8; nt++)
#pragma unroll
        for (int r = 0; r < 4; r++) O[nt][r] = 0.f;
    float m0 = -1e30f, m1 = -1e30f, l0 = 0.f, l1 = 0.f;

    for (int jt = 0; jt <= qt; jt++) {
        const int j0 = jt * 64;
        __syncthreads();
#pragma unroll
        for (int i = 0; i < 8; i++) {
            const int f = tid + 128*i;
            const int row = f >> 4, c4 = f & 15;
            float4 kv = *(const float4*)(Kg + (size_t)(j0+row)*DHEAD + c4*4);
            float4 vv = *(const float4*)(Vg + (size_t)(j0+row)*DHEAD + c4*4);
            // K: swizzled column placement (16B-granular, uint4-safe)
            *(uint4*)(Ks + row*AT_STR + ((c4*4) ^ ((row & 7) << 2))) =
                make_uint4(f2tf32(kv.x), f2tf32(kv.y), f2tf32(kv.z), f2tf32(kv.w));
            *(uint4*)(Vs + row*AT_STR + c4*4) =
                make_uint4(f2tf32(vv.x), f2tf32(vv.y), f2tf32(vv.z), f2tf32(vv.w));
        }
        __syncthreads();

        // S = Q K^T (16x64 per warp)
        float s[8][4];
#pragma unroll
        for (int nt = 0; nt < 8; nt++)
#pragma unroll
            for (int r = 0; r < 4; r++) s[nt][r] = 0.f;

#pragma unroll
        for (int k0 = 0; k0 < 64; k0 += 8) {
            uint32_t a[4];
            a[0] = Qs[r0*AT_STR + k0 + ig];
            a[1] = Qs[(r0+8)*AT_STR + k0 + ig];
            a[2] = Qs[r0*AT_STR + k0 + ig + 4];
            a[3] = Qs[(r0+8)*AT_STR + k0 + ig + 4];
            const int swk = g << 2;
#pragma unroll
            for (int nt = 0; nt < 8; nt++) {
                uint32_t b[2];
                b[0] = Ks[(nt*8+g)*AT_STR + ((k0 + ig) ^ swk)];
                b[1] = Ks[(nt*8+g)*AT_STR + ((k0 + ig + 4) ^ swk)];
                mma8(s[nt], a, b);
            }
        }

        if (jt == qt) {
            const int qa = q0 + r0, qb = qa + 8;
#pragma unroll
            for (int nt = 0; nt < 8; nt++) {
                const int j = j0 + nt*8 + 2*ig;
                if (j     > qa) s[nt][0] = -1e30f;
                if (j + 1 > qa) s[nt][1] = -1e30f;
                if (j     > qb) s[nt][2] = -1e30f;
                if (j + 1 > qb) s[nt][3] = -1e30f;
            }
        }

        float a0 = -1e30f, a1 = -1e30f;
#pragma unroll
        for (int nt = 0; nt < 8; nt++) {
            a0 = fmaxf(a0, fmaxf(s[nt][0], s[nt][1]));
            a1 = fmaxf(a1, fmaxf(s[nt][2], s[nt][3]));
        }
        a0 = fmaxf(a0, __shfl_xor_sync(0xFFFFFFFFu, a0, 1));
        a0 = fmaxf(a0, __shfl_xor_sync(0xFFFFFFFFu, a0, 2));
        a1 = fmaxf(a1, __shfl_xor_sync(0xFFFFFFFFu, a1, 1));
        a1 = fmaxf(a1, __shfl_xor_sync(0xFFFFFFFFu, a1, 2));

        const float mn0 = fmaxf(m0, a0), mn1 = fmaxf(m1, a1);
        const float c0 = __expf(m0 - mn0), c1 = __expf(m1 - mn1);
        l0 *= c0; l1 *= c1;
#pragma unroll
        for (int nt = 0; nt < 8; nt++) {
            O[nt][0] *= c0; O[nt][1] *= c0;
            O[nt][2] *= c1; O[nt][3] *= c1;
        }

        float t0 = 0.f, t1 = 0.f;
#pragma unroll
        for (int nt = 0; nt < 8; nt++) {
            const float p0 = __expf(s[nt][0] - mn0);
            const float p1 = __expf(s[nt][1] - mn0);
            const float p2 = __expf(s[nt][2] - mn1);
            const float p3 = __expf(s[nt][3] - mn1);
            t0 += p0 + p1; t1 += p2 + p3;
            *(uint2*)(Ps + r0*AT_STR + nt*8 + 2*ig)     = make_uint2(f2tf32(p0), f2tf32(p1));
            *(uint2*)(Ps + (r0+8)*AT_STR + nt*8 + 2*ig) = make_uint2(f2tf32(p2), f2tf32(p3));
        }
        t0 += __shfl_xor_sync(0xFFFFFFFFu, t0, 1);
        t0 += __shfl_xor_sync(0xFFFFFFFFu, t0, 2);
        t1 += __shfl_xor_sync(0xFFFFFFFFu, t1, 1);
        t1 += __shfl_xor_sync(0xFFFFFFFFu, t1, 2);
        l0 += t0; l1 += t1;
        m0 = mn0; m1 = mn1;
        __syncwarp();

        // O += P @ V (per-warp P rows; warp-local sync only)
#pragma unroll
        for (int k0 = 0; k0 < 64; k0 += 8) {
            uint32_t a[4];
            a[0] = Ps[r0*AT_STR + k0 + ig];
            a[1] = Ps[(r0+8)*AT_STR + k0 + ig];
            a[2] = Ps[r0*AT_STR + k0 + ig + 4];
            a[3] = Ps[(r0+8)*AT_STR + k0 + ig + 4];
#pragma unroll
            for (int nt = 0; nt < 8; nt++) {
                uint32_t b[2];
                b[0] = Vs[(k0+ig)*AT_STR + nt*8 + g];
                b[1] = Vs[(k0+ig+4)*AT_STR + nt*8 + g];
                mma8(O[nt], a, b);
            }
        }
        __syncwarp();
    }

    const float inv0 = 1.f / l0, inv1 = 1.f / l1;
    const int b = bh >> 4, h = bh & 15;
    float* base = g_att + ((size_t)(b*TSEQ + q0 + r0))*CDIM + h*DHEAD;
#pragma unroll
    for (int nt = 0; nt < 8; nt++) {
        *(float2*)(base + nt*8 + 2*ig) =
            make_float2(O[nt][0]*inv0, O[nt][1]*inv0);
        *(float2*)(base + (size_t)8*CDIM + nt*8 + 2*ig) =
            make_float2(O[nt][2]*inv1, O[nt][3]*inv1);
    }
}

// ---------------- launch ----------------
extern "C" void kernel_launch(void* const* d_in, const int* in_sizes, int n_in,
                              void* d_out, int out_size)
{
    (void)in_sizes; (void)n_in; (void)out_size;
    const float* x     = (const float*)d_in[0];
    const float* w_qkv = (const float*)d_in[1];
    const float* b_qkv = (const float*)d_in[2];
    const float* w_out = (const float*)d_in[3];
    const float* b_out = (const float*)d_in[4];
    float* out = (float*)d_out;

    cudaFuncSetAttribute(mm_kernel,   cudaFuncAttributeMaxDynamicSharedMemorySize, MM_SMEM);
    cudaFuncSetAttribute(attn_kernel, cudaFuncAttributeMaxDynamicSharedMemorySize, AT_SMEM);

    // 1) QKV projection (mma.sync tf32, cp.async pipeline) + bias + head-split scatter
    mm_kernel<<<dim3(3072/128, MROWS/128), 256, MM_SMEM>>>(x, w_qkv, b_qkv, nullptr, 3072, 0);
    // 2) causal flash attention (mma.sync tf32, conflict-free K)
    attn_kernel<<<dim3(TSEQ/64, BSZ*HH), 128, AT_SMEM>>>();
    // 3) output projection + bias
    mm_kernel<<<dim3(1024/128, MROWS/128), 256, MM_SMEM>>>(nullptr, w_out, b_out, out, 1024, 1);
}

// round 7
// speedup vs baseline: 3.7014x; 1.0658x over previous
#include <cuda_runtime.h>
#include <cstdint>

#define BSZ  4
#define TSEQ 2048
#define CDIM 1024
#define HH   16
#define DHEAD 64
#define MROWS (BSZ*TSEQ)   // 8192
#define KDIM 1024

// ---------------- device scratch (allocation-free rule) ----------------
// All internal tensors hold tf32 BIT PATTERNS stored as float words.
__device__ __align__(16) float g_q[(size_t)BSZ*HH*TSEQ*DHEAD];
__device__ __align__(16) float g_k[(size_t)BSZ*HH*TSEQ*DHEAD];
__device__ __align__(16) float g_v[(size_t)BSZ*HH*TSEQ*DHEAD];
__device__ __align__(16) float g_att[(size_t)MROWS*CDIM];
__device__ __align__(16) float g_xt[(size_t)MROWS*CDIM];        // x in tf32 bits
__device__ __align__(16) float g_wq[(size_t)KDIM*3*CDIM];       // w_qkv in tf32 bits
__device__ __align__(16) float g_wo[(size_t)KDIM*CDIM];         // w_out in tf32 bits

// ---------------- helpers ----------------
__device__ __forceinline__ uint32_t f2tf32(float f) {
    uint32_t r;
    asm("cvt.rna.tf32.f32 %0, %1;" : "=r"(r) : "f"(f));
    return r;
}

__device__ __forceinline__ void mma8(float* d, const uint32_t* a, const uint32_t* b) {
    asm("mma.sync.aligned.m16n8k8.row.col.f32.tf32.tf32.f32 "
        "{%0,%1,%2,%3}, {%4,%5,%6,%7}, {%8,%9}, {%0,%1,%2,%3};"
        : "+f"(d[0]), "+f"(d[1]), "+f"(d[2]), "+f"(d[3])
        : "r"(a[0]), "r"(a[1]), "r"(a[2]), "r"(a[3]), "r"(b[0]), "r"(b[1]));
}

__device__ __forceinline__ uint32_t smem_u32(const void* p) {
    uint32_t a;
    asm("{ .reg .u64 t; cvta.to.shared.u64 t, %1; cvt.u32.u64 %0, t; }" : "=r"(a) : "l"(p));
    return a;
}

__device__ __forceinline__ void cp16(uint32_t s, const void* g) {
    asm volatile("cp.async.cg.shared.global [%0], [%1], 16;" :: "r"(s), "l"(g));
}
#define CP_COMMIT() asm volatile("cp.async.commit_group;" ::: "memory")
#define CP_WAIT1()  asm volatile("cp.async.wait_group 1;" ::: "memory")

// ---------------- elementwise tf32 pre-convert ----------------
__global__ __launch_bounds__(256)
void cvt_kernel(const float4* __restrict__ src, uint4* __restrict__ dst, int n4)
{
    const int i = blockIdx.x * 256 + threadIdx.x;
    if (i < n4) {
        float4 v = src[i];
        dst[i] = make_uint4(f2tf32(v.x), f2tf32(v.y), f2tf32(v.z), f2tf32(v.w));
    }
}

// ---------------- tf32 mma.sync GEMM, cp.async 3-stage, no in-loop cvt ----------------
#define BK 32
#define AS_STR 36
#define A_WORDS (128*AS_STR)            // 4608
#define B_WORDS (BK*128)                // 4096
#define ST_WORDS (A_WORDS + B_WORDS)    // 8704
#define STAGES 3
#define MM_SMEM (STAGES*ST_WORDS*4)     // 104448 B

__global__ __launch_bounds__(256, 2)
void mm_kernel(const float* __restrict__ A, const float* __restrict__ Bw,
               const float* __restrict__ bias, float* __restrict__ Cout,
               int N, int mode)
{
    extern __shared__ uint32_t sm[];
    const uint32_t sb = smem_u32(sm);

    const int tid  = threadIdx.x;
    const int lane = tid & 31;
    const int warp = tid >> 5;
    const int wm = (warp >> 2) * 64;
    const int wn = (warp & 3) * 32;
    const int g  = lane >> 2;
    const int ig = lane & 3;

    const int m0 = blockIdx.y * 128;
    const int n0 = blockIdx.x * 128;

    if (mode) A = g_att;

    float d[4][4][4];
#pragma unroll
    for (int mt = 0; mt < 4; mt++)
#pragma unroll
        for (int nt = 0; nt < 4; nt++)
#pragma unroll
            for (int r = 0; r < 4; r++) d[mt][nt][r] = 0.f;

#define LDG_ASYNC(c, st) do {                                                     \
    uint32_t _sa = sb + (st)*ST_WORDS*4;                                          \
    uint32_t _sbB = _sa + A_WORDS*4;                                              \
    _Pragma("unroll") for (int i = 0; i < 4; i++) {                               \
        int idx = tid + 256*i; int row = idx >> 3, k4 = idx & 7;                  \
        cp16(_sa + (row*AS_STR + k4*4)*4,                                         \
             A + (size_t)(m0 + row)*KDIM + (c)*BK + k4*4); }                      \
    _Pragma("unroll") for (int i = 0; i < 4; i++) {                               \
        int idx = tid + 256*i; int k = idx >> 5, n4 = idx & 31;                   \
        cp16(_sbB + (k*128 + ((n4*4) ^ ((k&3)<<3)))*4,                            \
             Bw + (size_t)((c)*BK + k)*N + n0 + n4*4); }                          \
} while (0)

#define COMPUTE(st) do {                                                          \
    const uint32_t* Ap = sm + (st)*ST_WORDS;                                      \
    const uint32_t* Bp = Ap + A_WORDS;                                            \
    _Pragma("unroll") for (int s = 0; s < 4; s++) {                               \
        const int k0 = s*8;                                                       \
        uint32_t af[4][4], bf[4][2];                                              \
        _Pragma("unroll") for (int mt = 0; mt < 4; mt++) {                        \
            const int r = wm + mt*16 + g;                                         \
            af[mt][0] = Ap[r*AS_STR + k0 + ig];                                   \
            af[mt][1] = Ap[(r+8)*AS_STR + k0 + ig];                               \
            af[mt][2] = Ap[r*AS_STR + k0 + ig + 4];                               \
            af[mt][3] = Ap[(r+8)*AS_STR + k0 + ig + 4];                           \
        }                                                                         \
        _Pragma("unroll") for (int nt = 0; nt < 4; nt++) {                        \
            const int nn = wn + nt*8 + g;                                         \
            const int sw = ig << 3;                                               \
            bf[nt][0] = Bp[(k0+ig)*128 + (nn ^ sw)];                              \
            bf[nt][1] = Bp[(k0+4+ig)*128 + (nn ^ sw)];                            \
        }                                                                         \
        _Pragma("unroll") for (int mt = 0; mt < 4; mt++)                          \
            _Pragma("unroll") for (int nt = 0; nt < 4; nt++)                      \
                mma8(d[mt][nt], af[mt], bf[nt]);                                  \
    }                                                                             \
} while (0)

    LDG_ASYNC(0, 0); CP_COMMIT();
    LDG_ASYNC(1, 1); CP_COMMIT();

#pragma unroll 1
    for (int c = 0; c < KDIM/BK; c++) {
        CP_WAIT1();
        __syncthreads();
        if (c + 2 < KDIM/BK) {
            const int st = (c + 2) % STAGES;
            LDG_ASYNC(c + 2, st);
        }
        CP_COMMIT();
        COMPUTE(c % STAGES);
    }

    // ---- epilogue
#pragma unroll
    for (int mt = 0; mt < 4; mt++) {
        const int r0 = m0 + wm + mt*16 + g;
#pragma unroll
        for (int nt = 0; nt < 4; nt++) {
            const int c0 = n0 + wn + nt*8 + ig*2;
            const float b0 = bias[c0], b1 = bias[c0+1];
            if (mode == 0) {
                // write Q (pre-scaled) / K / V as tf32 bits
                const int sec = c0 >> 10;
                const int h   = (c0 & 1023) >> 6;
                const int dd  = c0 & 63;
                float* dstp = (sec == 0) ? g_q : ((sec == 1) ? g_k : g_v);
                const float scale = (sec == 0) ? 0.125f : 1.0f;
#pragma unroll
                for (int rr = 0; rr < 2; rr++) {
                    const int r = r0 + rr*8;
                    const int b = r >> 11, t = r & 2047;
                    uint2 v = make_uint2(f2tf32((d[mt][nt][rr*2+0] + b0) * scale),
                                         f2tf32((d[mt][nt][rr*2+1] + b1) * scale));
                    *(uint2*)(dstp + (((size_t)(b*HH + h))*TSEQ + t)*DHEAD + dd) = v;
                }
            } else {
#pragma unroll
                for (int rr = 0; rr < 2; rr++) {
                    const int r = r0 + rr*8;
                    float2 v = make_float2(d[mt][nt][rr*2+0] + b0, d[mt][nt][rr*2+1] + b1);
                    *(float2*)(Cout + (size_t)r*N + c0) = v;
                }
            }
        }
    }
}

// ---------------- tensor-core flash attention (tf32, no Q/K/V cvt) ----------------
#define AT_STR 76
#define AT_SMEM (4*64*AT_STR*4)   // 77824 B

__global__ __launch_bounds__(128, 2)
void attn_kernel()
{
    extern __shared__ uint32_t smu[];
    uint32_t* Qs = smu;
    uint32_t* Ks = Qs + 64*AT_STR;
    uint32_t* Vs = Ks + 64*AT_STR;
    uint32_t* Ps = Vs + 64*AT_STR;

    const int tid  = threadIdx.x;
    const int lane = tid & 31;
    const int w    = tid >> 5;
    const int g    = lane >> 2;
    const int ig   = lane & 3;
    const int bh = blockIdx.y;
    const int qt = (gridDim.x - 1) - blockIdx.x;   // long blocks first
    const int q0 = qt * 64;

    const uint32_t* Qg = (const uint32_t*)g_q + (size_t)bh * TSEQ * DHEAD;
    const uint32_t* Kg = (const uint32_t*)g_k + (size_t)bh * TSEQ * DHEAD;
    const uint32_t* Vg = (const uint32_t*)g_v + (size_t)bh * TSEQ * DHEAD;

    // Q already scaled + tf32: raw copy
#pragma unroll
    for (int i = 0; i < 8; i++) {
        const int f = tid + 128*i;
        const int row = f >> 4, c4 = f & 15;
        *(uint4*)(Qs + row*AT_STR + c4*4) =
            *(const uint4*)(Qg + (size_t)(q0+row)*DHEAD + c4*4);
    }

    const int r0 = 16*w + g;
    float O[8][4];
#pragma unroll
    for (int nt = 0; nt < 8; nt++)
#pragma unroll
        for (int r = 0; r < 4; r++) O[nt][r] = 0.f;
    float m0 = -1e30f, m1 = -1e30f, l0 = 0.f, l1 = 0.f;

    for (int jt = 0; jt <= qt; jt++) {
        const int j0 = jt * 64;
        __syncthreads();
#pragma unroll
        for (int i = 0; i < 8; i++) {
            const int f = tid + 128*i;
            const int row = f >> 4, c4 = f & 15;
            // K: swizzled column placement (16B-granular)
            *(uint4*)(Ks + row*AT_STR + ((c4*4) ^ ((row & 7) << 2))) =
                *(const uint4*)(Kg + (size_t)(j0+row)*DHEAD + c4*4);
            *(uint4*)(Vs + row*AT_STR + c4*4) =
                *(const uint4*)(Vg + (size_t)(j0+row)*DHEAD + c4*4);
        }
        __syncthreads();

        // S = Q K^T
        float s[8][4];
#pragma unroll
        for (int nt = 0; nt < 8; nt++)
#pragma unroll
            for (int r = 0; r < 4; r++) s[nt][r] = 0.f;

#pragma unroll
        for (int k0 = 0; k0 < 64; k0 += 8) {
            uint32_t a[4];
            a[0] = Qs[r0*AT_STR + k0 + ig];
            a[1] = Qs[(r0+8)*AT_STR + k0 + ig];
            a[2] = Qs[r0*AT_STR + k0 + ig + 4];
            a[3] = Qs[(r0+8)*AT_STR + k0 + ig + 4];
            const int swk = g << 2;
#pragma unroll
            for (int nt = 0; nt < 8; nt++) {
                uint32_t b[2];
                b[0] = Ks[(nt*8+g)*AT_STR + ((k0 + ig) ^ swk)];
                b[1] = Ks[(nt*8+g)*AT_STR + ((k0 + ig + 4) ^ swk)];
                mma8(s[nt], a, b);
            }
        }

        if (jt == qt) {
            const int qa = q0 + r0, qb = qa + 8;
#pragma unroll
            for (int nt = 0; nt < 8; nt++) {
                const int j = j0 + nt*8 + 2*ig;
                if (j     > qa) s[nt][0] = -1e30f;
                if (j + 1 > qa) s[nt][1] = -1e30f;
                if (j     > qb) s[nt][2] = -1e30f;
                if (j + 1 > qb) s[nt][3] = -1e30f;
            }
        }

        float a0 = -1e30f, a1 = -1e30f;
#pragma unroll
        for (int nt = 0; nt < 8; nt++) {
            a0 = fmaxf(a0, fmaxf(s[nt][0], s[nt][1]));
            a1 = fmaxf(a1, fmaxf(s[nt][2], s[nt][3]));
        }
        a0 = fmaxf(a0, __shfl_xor_sync(0xFFFFFFFFu, a0, 1));
        a0 = fmaxf(a0, __shfl_xor_sync(0xFFFFFFFFu, a0, 2));
        a1 = fmaxf(a1, __shfl_xor_sync(0xFFFFFFFFu, a1, 1));
        a1 = fmaxf(a1, __shfl_xor_sync(0xFFFFFFFFu, a1, 2));

        const float mn0 = fmaxf(m0, a0), mn1 = fmaxf(m1, a1);
        const float c0 = __expf(m0 - mn0), c1 = __expf(m1 - mn1);
        l0 *= c0; l1 *= c1;
#pragma unroll
        for (int nt = 0; nt < 8; nt++) {
            O[nt][0] *= c0; O[nt][1] *= c0;
            O[nt][2] *= c1; O[nt][3] *= c1;
        }

        float t0 = 0.f, t1 = 0.f;
#pragma unroll
        for (int nt = 0; nt < 8; nt++) {
            const float p0 = __expf(s[nt][0] - mn0);
            const float p1 = __expf(s[nt][1] - mn0);
            const float p2 = __expf(s[nt][2] - mn1);
            const float p3 = __expf(s[nt][3] - mn1);
            t0 += p0 + p1; t1 += p2 + p3;
            *(uint2*)(Ps + r0*AT_STR + nt*8 + 2*ig)     = make_uint2(f2tf32(p0), f2tf32(p1));
            *(uint2*)(Ps + (r0+8)*AT_STR + nt*8 + 2*ig) = make_uint2(f2tf32(p2), f2tf32(p3));
        }
        t0 += __shfl_xor_sync(0xFFFFFFFFu, t0, 1);
        t0 += __shfl_xor_sync(0xFFFFFFFFu, t0, 2);
        t1 += __shfl_xor_sync(0xFFFFFFFFu, t1, 1);
        t1 += __shfl_xor_sync(0xFFFFFFFFu, t1, 2);
        l0 += t0; l1 += t1;
        m0 = mn0; m1 = mn1;
        __syncwarp();

        // O += P @ V
#pragma unroll
        for (int k0 = 0; k0 < 64; k0 += 8) {
            uint32_t a[4];
            a[0] = Ps[r0*AT_STR + k0 + ig];
            a[1] = Ps[(r0+8)*AT_STR + k0 + ig];
            a[2] = Ps[r0*AT_STR + k0 + ig + 4];
            a[3] = Ps[(r0+8)*AT_STR + k0 + ig + 4];
#pragma unroll
            for (int nt = 0; nt < 8; nt++) {
                uint32_t b[2];
                b[0] = Vs[(k0+ig)*AT_STR + nt*8 + g];
                b[1] = Vs[(k0+ig+4)*AT_STR + nt*8 + g];
                mma8(O[nt], a, b);
            }
        }
        __syncwarp();
    }

    // normalize, write g_att as tf32 bits (out-proj consumes bits directly)
    const float inv0 = 1.f / l0, inv1 = 1.f / l1;
    const int b = bh >> 4, h = bh & 15;
    uint32_t* base = (uint32_t*)g_att + ((size_t)(b*TSEQ + q0 + r0))*CDIM + h*DHEAD;
#pragma unroll
    for (int nt = 0; nt < 8; nt++) {
        *(uint2*)(base + nt*8 + 2*ig) =
            make_uint2(f2tf32(O[nt][0]*inv0), f2tf32(O[nt][1]*inv0));
        *(uint2*)(base + (size_t)8*CDIM + nt*8 + 2*ig) =
            make_uint2(f2tf32(O[nt][2]*inv1), f2tf32(O[nt][3]*inv1));
    }
}

// ---------------- launch ----------------
extern "C" void kernel_launch(void* const* d_in, const int* in_sizes, int n_in,
                              void* d_out, int out_size)
{
    (void)in_sizes; (void)n_in; (void)out_size;
    const float* x     = (const float*)d_in[0];
    const float* w_qkv = (const float*)d_in[1];
    const float* b_qkv = (const float*)d_in[2];
    const float* w_out = (const float*)d_in[3];
    const float* b_out = (const float*)d_in[4];
    float* out = (float*)d_out;

    cudaFuncSetAttribute(mm_kernel,   cudaFuncAttributeMaxDynamicSharedMemorySize, MM_SMEM);
    cudaFuncSetAttribute(attn_kernel, cudaFuncAttributeMaxDynamicSharedMemorySize, AT_SMEM);

    float *xt, *wq, *wo;
    cudaGetSymbolAddress((void**)&xt, g_xt);
    cudaGetSymbolAddress((void**)&wq, g_wq);
    cudaGetSymbolAddress((void**)&wo, g_wo);

    // 0) one-shot tf32 pre-conversion of external fp32 operands
    cvt_kernel<<<(MROWS*CDIM/4 + 255)/256, 256>>>((const float4*)x,     (uint4*)xt, MROWS*CDIM/4);
    cvt_kernel<<<(KDIM*3*CDIM/4 + 255)/256, 256>>>((const float4*)w_qkv, (uint4*)wq, KDIM*3*CDIM/4);
    cvt_kernel<<<(KDIM*CDIM/4   + 255)/256, 256>>>((const float4*)w_out, (uint4*)wo, KDIM*CDIM/4);

    // 1) QKV projection + bias + head-split scatter (emits tf32-bit Q/K/V, Q pre-scaled)
    mm_kernel<<<dim3(3072/128, MROWS/128), 256, MM_SMEM>>>(xt, wq, b_qkv, nullptr, 3072, 0);
    // 2) causal flash attention (emits tf32-bit g_att)
    attn_kernel<<<dim3(TSEQ/64, BSZ*HH), 128, AT_SMEM>>>();
    // 3) output projection + bias (fp32 out)
    mm_kernel<<<dim3(1024/128, MROWS/128), 256, MM_SMEM>>>(nullptr, wo, b_out, out, 1024, 1);
}

// round 8
// speedup vs baseline: 4.9432x; 1.3355x over previous
#include <cuda_runtime.h>
#include <cstdint>

#define BSZ  4
#define TSEQ 2048
#define CDIM 1024
#define HH   16
#define DHEAD 64
#define MROWS (BSZ*TSEQ)   // 8192
#define KDIM 1024

// ---------------- device scratch (allocation-free rule) ----------------
// All internal tensors hold tf32 BIT PATTERNS stored as float words.
__device__ __align__(16) float g_q[(size_t)BSZ*HH*TSEQ*DHEAD];
__device__ __align__(16) float g_k[(size_t)BSZ*HH*TSEQ*DHEAD];
__device__ __align__(16) float g_v[(size_t)BSZ*HH*TSEQ*DHEAD];
__device__ __align__(16) float g_att[(size_t)MROWS*CDIM];
__device__ __align__(16) float g_xt[(size_t)MROWS*CDIM];
__device__ __align__(16) float g_wq[(size_t)KDIM*3*CDIM];
__device__ __align__(16) float g_wo[(size_t)KDIM*CDIM];

// ---------------- helpers ----------------
__device__ __forceinline__ uint32_t f2tf32(float f) {
    uint32_t r;
    asm("cvt.rna.tf32.f32 %0, %1;" : "=r"(r) : "f"(f));
    return r;
}

__device__ __forceinline__ void mma8(float* d, const uint32_t* a, const uint32_t* b) {
    asm("mma.sync.aligned.m16n8k8.row.col.f32.tf32.tf32.f32 "
        "{%0,%1,%2,%3}, {%4,%5,%6,%7}, {%8,%9}, {%0,%1,%2,%3};"
        : "+f"(d[0]), "+f"(d[1]), "+f"(d[2]), "+f"(d[3])
        : "r"(a[0]), "r"(a[1]), "r"(a[2]), "r"(a[3]), "r"(b[0]), "r"(b[1]));
}

__device__ __forceinline__ uint32_t smem_u32(const void* p) {
    uint32_t a;
    asm("{ .reg .u64 t; cvta.to.shared.u64 t, %1; cvt.u32.u64 %0, t; }" : "=r"(a) : "l"(p));
    return a;
}

__device__ __forceinline__ void cp16(uint32_t s, const void* g) {
    asm volatile("cp.async.cg.shared.global [%0], [%1], 16;" :: "r"(s), "l"(g));
}
#define CP_COMMIT() asm volatile("cp.async.commit_group;" ::: "memory")
#define CP_WAIT1()  asm volatile("cp.async.wait_group 1;" ::: "memory")
#define CP_WAIT0()  asm volatile("cp.async.wait_group 0;" ::: "memory")

// ---------------- elementwise tf32 pre-convert ----------------
__global__ __launch_bounds__(256)
void cvt_kernel(const float4* __restrict__ src, uint4* __restrict__ dst, int n4)
{
    const int i = blockIdx.x * 256 + threadIdx.x;
    if (i < n4) {
        float4 v = src[i];
        dst[i] = make_uint4(f2tf32(v.x), f2tf32(v.y), f2tf32(v.z), f2tf32(v.w));
    }
}

// ---------------- tf32 mma.sync GEMM, cp.async 3-stage (unchanged from R7) ----------------
#define BK 32
#define AS_STR 36
#define A_WORDS (128*AS_STR)
#define B_WORDS (BK*128)
#define ST_WORDS (A_WORDS + B_WORDS)
#define STAGES 3
#define MM_SMEM (STAGES*ST_WORDS*4)

__global__ __launch_bounds__(256, 2)
void mm_kernel(const float* __restrict__ A, const float* __restrict__ Bw,
               const float* __restrict__ bias, float* __restrict__ Cout,
               int N, int mode)
{
    extern __shared__ uint32_t sm[];
    const uint32_t sb = smem_u32(sm);

    const int tid  = threadIdx.x;
    const int lane = tid & 31;
    const int warp = tid >> 5;
    const int wm = (warp >> 2) * 64;
    const int wn = (warp & 3) * 32;
    const int g  = lane >> 2;
    const int ig = lane & 3;

    const int m0 = blockIdx.y * 128;
    const int n0 = blockIdx.x * 128;

    if (mode) A = g_att;

    float d[4][4][4];
#pragma unroll
    for (int mt = 0; mt < 4; mt++)
#pragma unroll
        for (int nt = 0; nt < 4; nt++)
#pragma unroll
            for (int r = 0; r < 4; r++) d[mt][nt][r] = 0.f;

#define LDG_ASYNC(c, st) do {                                                     \
    uint32_t _sa = sb + (st)*ST_WORDS*4;                                          \
    uint32_t _sbB = _sa + A_WORDS*4;                                              \
    _Pragma("unroll") for (int i = 0; i < 4; i++) {                               \
        int idx = tid + 256*i; int row = idx >> 3, k4 = idx & 7;                  \
        cp16(_sa + (row*AS_STR + k4*4)*4,                                         \
             A + (size_t)(m0 + row)*KDIM + (c)*BK + k4*4); }                      \
    _Pragma("unroll") for (int i = 0; i < 4; i++) {                               \
        int idx = tid + 256*i; int k = idx >> 5, n4 = idx & 31;                   \
        cp16(_sbB + (k*128 + ((n4*4) ^ ((k&3)<<3)))*4,                            \
             Bw + (size_t)((c)*BK + k)*N + n0 + n4*4); }                          \
} while (0)

#define COMPUTE(st) do {                                                          \
    const uint32_t* Ap = sm + (st)*ST_WORDS;                                      \
    const uint32_t* Bp = Ap + A_WORDS;                                            \
    _Pragma("unroll") for (int s = 0; s < 4; s++) {                               \
        const int k0 = s*8;                                                       \
        uint32_t af[4][4], bf[4][2];                                              \
        _Pragma("unroll") for (int mt = 0; mt < 4; mt++) {                        \
            const int r = wm + mt*16 + g;                                         \
            af[mt][0] = Ap[r*AS_STR + k0 + ig];                                   \
            af[mt][1] = Ap[(r+8)*AS_STR + k0 + ig];                               \
            af[mt][2] = Ap[r*AS_STR + k0 + ig + 4];                               \
            af[mt][3] = Ap[(r+8)*AS_STR + k0 + ig + 4];                           \
        }                                                                         \
        _Pragma("unroll") for (int nt = 0; nt < 4; nt++) {                        \
            const int nn = wn + nt*8 + g;                                         \
            const int sw = ig << 3;                                               \
            bf[nt][0] = Bp[(k0+ig)*128 + (nn ^ sw)];                              \
            bf[nt][1] = Bp[(k0+4+ig)*128 + (nn ^ sw)];                            \
        }                                                                         \
        _Pragma("unroll") for (int mt = 0; mt < 4; mt++)                          \
            _Pragma("unroll") for (int nt = 0; nt < 4; nt++)                      \
                mma8(d[mt][nt], af[mt], bf[nt]);                                  \
    }                                                                             \
} while (0)

    LDG_ASYNC(0, 0); CP_COMMIT();
    LDG_ASYNC(1, 1); CP_COMMIT();

#pragma unroll 1
    for (int c = 0; c < KDIM/BK; c++) {
        CP_WAIT1();
        __syncthreads();
        if (c + 2 < KDIM/BK) {
            const int st = (c + 2) % STAGES;
            LDG_ASYNC(c + 2, st);
        }
        CP_COMMIT();
        COMPUTE(c % STAGES);
    }

#pragma unroll
    for (int mt = 0; mt < 4; mt++) {
        const int r0 = m0 + wm + mt*16 + g;
#pragma unroll
        for (int nt = 0; nt < 4; nt++) {
            const int c0 = n0 + wn + nt*8 + ig*2;
            const float b0 = bias[c0], b1 = bias[c0+1];
            if (mode == 0) {
                const int sec = c0 >> 10;
                const int h   = (c0 & 1023) >> 6;
                const int dd  = c0 & 63;
                float* dstp = (sec == 0) ? g_q : ((sec == 1) ? g_k : g_v);
                const float scale = (sec == 0) ? 0.125f : 1.0f;
#pragma unroll
                for (int rr = 0; rr < 2; rr++) {
                    const int r = r0 + rr*8;
                    const int b = r >> 11, t = r & 2047;
                    uint2 v = make_uint2(f2tf32((d[mt][nt][rr*2+0] + b0) * scale),
                                         f2tf32((d[mt][nt][rr*2+1] + b1) * scale));
                    *(uint2*)(dstp + (((size_t)(b*HH + h))*TSEQ + t)*DHEAD + dd) = v;
                }
            } else {
#pragma unroll
                for (int rr = 0; rr < 2; rr++) {
                    const int r = r0 + rr*8;
                    float2 v = make_float2(d[mt][nt][rr*2+0] + b0, d[mt][nt][rr*2+1] + b1);
                    *(float2*)(Cout + (size_t)r*N + c0) = v;
                }
            }
        }
    }
}

// ---------------- tensor-core flash attention, cp.async double-buffered K/V ----------------
// Q/P: stride 76 (conflict-free for their patterns). K/V: stride 72, 2 stages each
// (K swizzled column ^((row&7)<<2): b-frag loads hit all 32 banks; V b-frags likewise).
#define QP_STR 76
#define KV_STR 72
#define Q_WORDS  (64*QP_STR)            // 4864
#define P_WORDS  (64*QP_STR)            // 4864
#define KV_WORDS (64*KV_STR)            // 4608
#define AT_SMEM ((Q_WORDS + P_WORDS + 4*KV_WORDS)*4)   // 112640 B

__global__ __launch_bounds__(128, 2)
void attn_kernel()
{
    extern __shared__ uint32_t smu[];
    uint32_t* Qs = smu;
    uint32_t* Ps = Qs + Q_WORDS;
    uint32_t* Kst = Ps + P_WORDS;                // 2 stages of K
    uint32_t* Vst = Kst + 2*KV_WORDS;            // 2 stages of V
    const uint32_t sb_k = smem_u32(Kst);
    const uint32_t sb_v = smem_u32(Vst);

    const int tid  = threadIdx.x;
    const int lane = tid & 31;
    const int w    = tid >> 5;
    const int g    = lane >> 2;
    const int ig   = lane & 3;
    const int bh = blockIdx.y;
    const int qt = (gridDim.x - 1) - blockIdx.x;   // long blocks first
    const int q0 = qt * 64;

    const uint32_t* Qg = (const uint32_t*)g_q + (size_t)bh * TSEQ * DHEAD;
    const uint32_t* Kg = (const uint32_t*)g_k + (size_t)bh * TSEQ * DHEAD;
    const uint32_t* Vg = (const uint32_t*)g_v + (size_t)bh * TSEQ * DHEAD;

#define PREFETCH_KV(j0, st) do {                                                  \
    uint32_t _kb = sb_k + (st)*KV_WORDS*4;                                        \
    uint32_t _vb = sb_v + (st)*KV_WORDS*4;                                        \
    _Pragma("unroll") for (int i = 0; i < 8; i++) {                               \
        int f = tid + 128*i; int row = f >> 4, c4 = f & 15;                       \
        cp16(_kb + (row*KV_STR + ((c4*4) ^ ((row & 7) << 2)))*4,                  \
             Kg + (size_t)((j0)+row)*DHEAD + c4*4);                               \
        cp16(_vb + (row*KV_STR + c4*4)*4,                                         \
             Vg + (size_t)((j0)+row)*DHEAD + c4*4);                               \
    }                                                                             \
} while (0)

    // Q already scaled + tf32: raw copy
#pragma unroll
    for (int i = 0; i < 8; i++) {
        const int f = tid + 128*i;
        const int row = f >> 4, c4 = f & 15;
        *(uint4*)(Qs + row*QP_STR + c4*4) =
            *(const uint4*)(Qg + (size_t)(q0+row)*DHEAD + c4*4);
    }

    PREFETCH_KV(0, 0);
    CP_COMMIT();

    const int r0 = 16*w + g;
    float O[8][4];
#pragma unroll
    for (int nt = 0; nt < 8; nt++)
#pragma unroll
        for (int r = 0; r < 4; r++) O[nt][r] = 0.f;
    float m0 = -1e30f, m1 = -1e30f, l0 = 0.f, l1 = 0.f;

#pragma unroll 1
    for (int jt = 0; jt <= qt; jt++) {
        const int j0 = jt * 64;
        const int p = jt & 1;

        CP_WAIT0();
        __syncthreads();          // tile jt ready; all threads done with stage p^1

        if (jt < qt) {
            PREFETCH_KV(j0 + 64, p ^ 1);
            CP_COMMIT();
        }

        const uint32_t* Ks = Kst + p*KV_WORDS;
        const uint32_t* Vs = Vst + p*KV_WORDS;

        // S = Q K^T
        float s[8][4];
#pragma unroll
        for (int nt = 0; nt < 8; nt++)
#pragma unroll
            for (int r = 0; r < 4; r++) s[nt][r] = 0.f;

#pragma unroll
        for (int k0 = 0; k0 < 64; k0 += 8) {
            uint32_t a[4];
            a[0] = Qs[r0*QP_STR + k0 + ig];
            a[1] = Qs[(r0+8)*QP_STR + k0 + ig];
            a[2] = Qs[r0*QP_STR + k0 + ig + 4];
            a[3] = Qs[(r0+8)*QP_STR + k0 + ig + 4];
            const int swk = g << 2;
#pragma unroll
            for (int nt = 0; nt < 8; nt++) {
                uint32_t b[2];
                b[0] = Ks[(nt*8+g)*KV_STR + ((k0 + ig) ^ swk)];
                b[1] = Ks[(nt*8+g)*KV_STR + ((k0 + ig + 4) ^ swk)];
                mma8(s[nt], a, b);
            }
        }

        if (jt == qt) {
            const int qa = q0 + r0, qb = qa + 8;
#pragma unroll
            for (int nt = 0; nt < 8; nt++) {
                const int j = j0 + nt*8 + 2*ig;
                if (j     > qa) s[nt][0] = -1e30f;
                if (j + 1 > qa) s[nt][1] = -1e30f;
                if (j     > qb) s[nt][2] = -1e30f;
                if (j + 1 > qb) s[nt][3] = -1e30f;
            }
        }

        float a0 = -1e30f, a1 = -1e30f;
#pragma unroll
        for (int nt = 0; nt < 8; nt++) {
            a0 = fmaxf(a0, fmaxf(s[nt][0], s[nt][1]));
            a1 = fmaxf(a1, fmaxf(s[nt][2], s[nt][3]));
        }
        a0 = fmaxf(a0, __shfl_xor_sync(0xFFFFFFFFu, a0, 1));
        a0 = fmaxf(a0, __shfl_xor_sync(0xFFFFFFFFu, a0, 2));
        a1 = fmaxf(a1, __shfl_xor_sync(0xFFFFFFFFu, a1, 1));
        a1 = fmaxf(a1, __shfl_xor_sync(0xFFFFFFFFu, a1, 2));

        const float mn0 = fmaxf(m0, a0), mn1 = fmaxf(m1, a1);
        const float c0 = __expf(m0 - mn0), c1 = __expf(m1 - mn1);
        l0 *= c0; l1 *= c1;
#pragma unroll
        for (int nt = 0; nt < 8; nt++) {
            O[nt][0] *= c0; O[nt][1] *= c0;
            O[nt][2] *= c1; O[nt][3] *= c1;
        }

        float t0 = 0.f, t1 = 0.f;
#pragma unroll
        for (int nt = 0; nt < 8; nt++) {
            const float p0 = __expf(s[nt][0] - mn0);
            const float p1 = __expf(s[nt][1] - mn0);
            const float p2 = __expf(s[nt][2] - mn1);
            const float p3 = __expf(s[nt][3] - mn1);
            t0 += p0 + p1; t1 += p2 + p3;
            *(uint2*)(Ps + r0*QP_STR + nt*8 + 2*ig)     = make_uint2(f2tf32(p0), f2tf32(p1));
            *(uint2*)(Ps + (r0+8)*QP_STR + nt*8 + 2*ig) = make_uint2(f2tf32(p2), f2tf32(p3));
        }
        t0 += __shfl_xor_sync(0xFFFFFFFFu, t0, 1);
        t0 += __shfl_xor_sync(0xFFFFFFFFu, t0, 2);
        t1 += __shfl_xor_sync(0xFFFFFFFFu, t1, 1);
        t1 += __shfl_xor_sync(0xFFFFFFFFu, t1, 2);
        l0 += t0; l1 += t1;
        m0 = mn0; m1 = mn1;
        __syncwarp();

        // O += P @ V
#pragma unroll
        for (int k0 = 0; k0 < 64; k0 += 8) {
            uint32_t a[4];
            a[0] = Ps[r0*QP_STR + k0 + ig];
            a[1] = Ps[(r0+8)*QP_STR + k0 + ig];
            a[2] = Ps[r0*QP_STR + k0 + ig + 4];
            a[3] = Ps[(r0+8)*QP_STR + k0 + ig + 4];
#pragma unroll
            for (int nt = 0; nt < 8; nt++) {
                uint32_t b[2];
                b[0] = Vs[(k0+ig)*KV_STR + nt*8 + g];
                b[1] = Vs[(k0+ig+4)*KV_STR + nt*8 + g];
                mma8(O[nt], a, b);
            }
        }
        __syncwarp();
    }

    // normalize, write g_att as tf32 bits
    const float inv0 = 1.f / l0, inv1 = 1.f / l1;
    const int b = bh >> 4, h = bh & 15;
    uint32_t* base = (uint32_t*)g_att + ((size_t)(b*TSEQ + q0 + r0))*CDIM + h*DHEAD;
#pragma unroll
    for (int nt = 0; nt < 8; nt++) {
        *(uint2*)(base + nt*8 + 2*ig) =
            make_uint2(f2tf32(O[nt][0]*inv0), f2tf32(O[nt][1]*inv0));
        *(uint2*)(base + (size_t)8*CDIM + nt*8 + 2*ig) =
            make_uint2(f2tf32(O[nt][2]*inv1), f2tf32(O[nt][3]*inv1));
    }
}

// ---------------- launch ----------------
extern "C" void kernel_launch(void* const* d_in, const int* in_sizes, int n_in,
                              void* d_out, int out_size)
{
    (void)in_sizes; (void)n_in; (void)out_size;
    const float* x     = (const float*)d_in[0];
    const float* w_qkv = (const float*)d_in[1];
    const float* b_qkv = (const float*)d_in[2];
    const float* w_out = (const float*)d_in[3];
    const float* b_out = (const float*)d_in[4];
    float* out = (float*)d_out;

    cudaFuncSetAttribute(mm_kernel,   cudaFuncAttributeMaxDynamicSharedMemorySize, MM_SMEM);
    cudaFuncSetAttribute(attn_kernel, cudaFuncAttributeMaxDynamicSharedMemorySize, AT_SMEM);

    float *xt, *wq, *wo;
    cudaGetSymbolAddress((void**)&xt, g_xt);
    cudaGetSymbolAddress((void**)&wq, g_wq);
    cudaGetSymbolAddress((void**)&wo, g_wo);

    // 0) one-shot tf32 pre-conversion of external fp32 operands
    cvt_kernel<<<(MROWS*CDIM/4 + 255)/256, 256>>>((const float4*)x,     (uint4*)xt, MROWS*CDIM/4);
    cvt_kernel<<<(KDIM*3*CDIM/4 + 255)/256, 256>>>((const float4*)w_qkv, (uint4*)wq, KDIM*3*CDIM/4);
    cvt_kernel<<<(KDIM*CDIM/4   + 255)/256, 256>>>((const float4*)w_out, (uint4*)wo, KDIM*CDIM/4);

    // 1) QKV projection + bias + head-split scatter (tf32-bit Q/K/V, Q pre-scaled)
    mm_kernel<<<dim3(3072/128, MROWS/128), 256, MM_SMEM>>>(xt, wq, b_qkv, nullptr, 3072, 0);
    // 2) causal flash attention (cp.async double-buffered K/V)
    attn_kernel<<<dim3(TSEQ/64, BSZ*HH), 128, AT_SMEM>>>();
    // 3) output projection + bias (fp32 out)
    mm_kernel<<<dim3(1024/128, MROWS/128), 256, MM_SMEM>>>(nullptr, wo, b_out, out, 1024, 1);
}

// round 9
// speedup vs baseline: 5.0296x; 1.0175x over previous
#include <cuda_runtime.h>
#include <cstdint>

#define BSZ  4
#define TSEQ 2048
#define CDIM 1024
#define HH   16
#define DHEAD 64
#define MROWS (BSZ*TSEQ)   // 8192
#define KDIM 1024

// ---------------- device scratch (allocation-free rule) ----------------
// All internal tensors hold tf32 BIT PATTERNS stored as float words.
__device__ __align__(16) float g_q[(size_t)BSZ*HH*TSEQ*DHEAD];
__device__ __align__(16) float g_k[(size_t)BSZ*HH*TSEQ*DHEAD];
__device__ __align__(16) float g_v[(size_t)BSZ*HH*TSEQ*DHEAD];
__device__ __align__(16) float g_att[(size_t)MROWS*CDIM];
__device__ __align__(16) float g_xt[(size_t)MROWS*CDIM];
__device__ __align__(16) float g_wq[(size_t)KDIM*3*CDIM];
__device__ __align__(16) float g_wo[(size_t)KDIM*CDIM];

// ---------------- helpers ----------------
__device__ __forceinline__ uint32_t f2tf32(float f) {
    uint32_t r;
    asm("cvt.rna.tf32.f32 %0, %1;" : "=r"(r) : "f"(f));
    return r;
}

__device__ __forceinline__ void mma8(float* d, const uint32_t* a, const uint32_t* b) {
    asm("mma.sync.aligned.m16n8k8.row.col.f32.tf32.tf32.f32 "
        "{%0,%1,%2,%3}, {%4,%5,%6,%7}, {%8,%9}, {%0,%1,%2,%3};"
        : "+f"(d[0]), "+f"(d[1]), "+f"(d[2]), "+f"(d[3])
        : "r"(a[0]), "r"(a[1]), "r"(a[2]), "r"(a[3]), "r"(b[0]), "r"(b[1]));
}

__device__ __forceinline__ uint32_t smem_u32(const void* p) {
    uint32_t a;
    asm("{ .reg .u64 t; cvta.to.shared.u64 t, %1; cvt.u32.u64 %0, t; }" : "=r"(a) : "l"(p));
    return a;
}

__device__ __forceinline__ void cp16(uint32_t s, const void* g) {
    asm volatile("cp.async.cg.shared.global [%0], [%1], 16;" :: "r"(s), "l"(g));
}
#define CP_COMMIT() asm volatile("cp.async.commit_group;" ::: "memory")
#define CP_WAIT1()  asm volatile("cp.async.wait_group 1;" ::: "memory")
#define CP_WAIT0()  asm volatile("cp.async.wait_group 0;" ::: "memory")

// ---------------- elementwise tf32 pre-convert ----------------
__global__ __launch_bounds__(256)
void cvt_kernel(const float4* __restrict__ src, uint4* __restrict__ dst, int n4)
{
    const int i = blockIdx.x * 256 + threadIdx.x;
    if (i < n4) {
        float4 v = src[i];
        dst[i] = make_uint4(f2tf32(v.x), f2tf32(v.y), f2tf32(v.z), f2tf32(v.w));
    }
}

// ---------------- tf32 mma.sync GEMM, cp.async 3-stage, warp tile 64x64 ----------------
// CTA tile 128x128, BK=32, 128 threads = 4 warps (2m x 2n), warp tile 64x64.
#define BK 32
#define AS_STR 36
#define A_WORDS (128*AS_STR)
#define B_WORDS (BK*128)
#define ST_WORDS (A_WORDS + B_WORDS)
#define STAGES 3
#define MM_SMEM (STAGES*ST_WORDS*4)

__global__ __launch_bounds__(128, 2)
void mm_kernel(const float* __restrict__ A, const float* __restrict__ Bw,
               const float* __restrict__ bias, float* __restrict__ Cout,
               int N, int mode)
{
    extern __shared__ uint32_t sm[];
    const uint32_t sb = smem_u32(sm);

    const int tid  = threadIdx.x;
    const int lane = tid & 31;
    const int warp = tid >> 5;
    const int wm = (warp >> 1) * 64;      // 0 or 64
    const int wn = (warp & 1) * 64;       // 0 or 64
    const int g  = lane >> 2;
    const int ig = lane & 3;

    const int m0 = blockIdx.y * 128;
    const int n0 = blockIdx.x * 128;

    if (mode) A = g_att;

    float d[4][8][4];
#pragma unroll
    for (int mt = 0; mt < 4; mt++)
#pragma unroll
        for (int nt = 0; nt < 8; nt++)
#pragma unroll
            for (int r = 0; r < 4; r++) d[mt][nt][r] = 0.f;

#define LDG_ASYNC(c, st) do {                                                     \
    uint32_t _sa = sb + (st)*ST_WORDS*4;                                          \
    uint32_t _sbB = _sa + A_WORDS*4;                                              \
    _Pragma("unroll") for (int i = 0; i < 8; i++) {                               \
        int idx = tid + 128*i; int row = idx >> 3, k4 = idx & 7;                  \
        cp16(_sa + (row*AS_STR + k4*4)*4,                                         \
             A + (size_t)(m0 + row)*KDIM + (c)*BK + k4*4); }                      \
    _Pragma("unroll") for (int i = 0; i < 8; i++) {                               \
        int idx = tid + 128*i; int k = idx >> 5, n4 = idx & 31;                   \
        cp16(_sbB + (k*128 + ((n4*4) ^ ((k&3)<<3)))*4,                            \
             Bw + (size_t)((c)*BK + k)*N + n0 + n4*4); }                          \
} while (0)

#define COMPUTE(st) do {                                                          \
    const uint32_t* Ap = sm + (st)*ST_WORDS;                                      \
    const uint32_t* Bp = Ap + A_WORDS;                                            \
    _Pragma("unroll") for (int s = 0; s < 4; s++) {                               \
        const int k0 = s*8;                                                       \
        uint32_t af[4][4], bf[8][2];                                              \
        _Pragma("unroll") for (int mt = 0; mt < 4; mt++) {                        \
            const int r = wm + mt*16 + g;                                         \
            af[mt][0] = Ap[r*AS_STR + k0 + ig];                                   \
            af[mt][1] = Ap[(r+8)*AS_STR + k0 + ig];                               \
            af[mt][2] = Ap[r*AS_STR + k0 + ig + 4];                               \
            af[mt][3] = Ap[(r+8)*AS_STR + k0 + ig + 4];                           \
        }                                                                         \
        _Pragma("unroll") for (int nt = 0; nt < 8; nt++) {                        \
            const int nn = wn + nt*8 + g;                                         \
            const int sw = ig << 3;                                               \
            bf[nt][0] = Bp[(k0+ig)*128 + (nn ^ sw)];                              \
            bf[nt][1] = Bp[(k0+4+ig)*128 + (nn ^ sw)];                            \
        }                                                                         \
        _Pragma("unroll") for (int mt = 0; mt < 4; mt++)                          \
            _Pragma("unroll") for (int nt = 0; nt < 8; nt++)                      \
                mma8(d[mt][nt], af[mt], bf[nt]);                                  \
    }                                                                             \
} while (0)

    LDG_ASYNC(0, 0); CP_COMMIT();
    LDG_ASYNC(1, 1); CP_COMMIT();

#pragma unroll 1
    for (int c = 0; c < KDIM/BK; c++) {
        CP_WAIT1();
        __syncthreads();
        if (c + 2 < KDIM/BK) {
            const int st = (c + 2) % STAGES;
            LDG_ASYNC(c + 2, st);
        }
        CP_COMMIT();
        COMPUTE(c % STAGES);
    }

#pragma unroll
    for (int mt = 0; mt < 4; mt++) {
        const int r0 = m0 + wm + mt*16 + g;
#pragma unroll
        for (int nt = 0; nt < 8; nt++) {
            const int c0 = n0 + wn + nt*8 + ig*2;
            const float b0 = bias[c0], b1 = bias[c0+1];
            if (mode == 0) {
                const int sec = c0 >> 10;
                const int h   = (c0 & 1023) >> 6;
                const int dd  = c0 & 63;
                float* dstp = (sec == 0) ? g_q : ((sec == 1) ? g_k : g_v);
                const float scale = (sec == 0) ? 0.125f : 1.0f;
#pragma unroll
                for (int rr = 0; rr < 2; rr++) {
                    const int r = r0 + rr*8;
                    const int b = r >> 11, t = r & 2047;
                    uint2 v = make_uint2(f2tf32((d[mt][nt][rr*2+0] + b0) * scale),
                                         f2tf32((d[mt][nt][rr*2+1] + b1) * scale));
                    *(uint2*)(dstp + (((size_t)(b*HH + h))*TSEQ + t)*DHEAD + dd) = v;
                }
            } else {
#pragma unroll
                for (int rr = 0; rr < 2; rr++) {
                    const int r = r0 + rr*8;
                    float2 v = make_float2(d[mt][nt][rr*2+0] + b0, d[mt][nt][rr*2+1] + b1);
                    *(float2*)(Cout + (size_t)r*N + c0) = v;
                }
            }
        }
    }
}

// ---------------- tensor-core flash attention, cp.async double-buffered K/V ----------------
// (unchanged from R8)
#define QP_STR 76
#define KV_STR 72
#define Q_WORDS  (64*QP_STR)
#define P_WORDS  (64*QP_STR)
#define KV_WORDS (64*KV_STR)
#define AT_SMEM ((Q_WORDS + P_WORDS + 4*KV_WORDS)*4)   // 112640 B

__global__ __launch_bounds__(128, 2)
void attn_kernel()
{
    extern __shared__ uint32_t smu[];
    uint32_t* Qs = smu;
    uint32_t* Ps = Qs + Q_WORDS;
    uint32_t* Kst = Ps + P_WORDS;
    uint32_t* Vst = Kst + 2*KV_WORDS;
    const uint32_t sb_k = smem_u32(Kst);
    const uint32_t sb_v = smem_u32(Vst);

    const int tid  = threadIdx.x;
    const int lane = tid & 31;
    const int w    = tid >> 5;
    const int g    = lane >> 2;
    const int ig   = lane & 3;
    const int bh = blockIdx.y;
    const int qt = (gridDim.x - 1) - blockIdx.x;
    const int q0 = qt * 64;

    const uint32_t* Qg = (const uint32_t*)g_q + (size_t)bh * TSEQ * DHEAD;
    const uint32_t* Kg = (const uint32_t*)g_k + (size_t)bh * TSEQ * DHEAD;
    const uint32_t* Vg = (const uint32_t*)g_v + (size_t)bh * TSEQ * DHEAD;

#define PREFETCH_KV(j0, st) do {                                                  \
    uint32_t _kb = sb_k + (st)*KV_WORDS*4;                                        \
    uint32_t _vb = sb_v + (st)*KV_WORDS*4;                                        \
    _Pragma("unroll") for (int i = 0; i < 8; i++) {                               \
        int f = tid + 128*i; int row = f >> 4, c4 = f & 15;                       \
        cp16(_kb + (row*KV_STR + ((c4*4) ^ ((row & 7) << 2)))*4,                  \
             Kg + (size_t)((j0)+row)*DHEAD + c4*4);                               \
        cp16(_vb + (row*KV_STR + c4*4)*4,                                         \
             Vg + (size_t)((j0)+row)*DHEAD + c4*4);                               \
    }                                                                             \
} while (0)

#pragma unroll
    for (int i = 0; i < 8; i++) {
        const int f = tid + 128*i;
        const int row = f >> 4, c4 = f & 15;
        *(uint4*)(Qs + row*QP_STR + c4*4) =
            *(const uint4*)(Qg + (size_t)(q0+row)*DHEAD + c4*4);
    }

    PREFETCH_KV(0, 0);
    CP_COMMIT();

    const int r0 = 16*w + g;
    float O[8][4];
#pragma unroll
    for (int nt = 0; nt < 8; nt++)
#pragma unroll
        for (int r = 0; r < 4; r++) O[nt][r] = 0.f;
    float m0 = -1e30f, m1 = -1e30f, l0 = 0.f, l1 = 0.f;

#pragma unroll 1
    for (int jt = 0; jt <= qt; jt++) {
        const int j0 = jt * 64;
        const int p = jt & 1;

        CP_WAIT0();
        __syncthreads();

        if (jt < qt) {
            PREFETCH_KV(j0 + 64, p ^ 1);
            CP_COMMIT();
        }

        const uint32_t* Ks = Kst + p*KV_WORDS;
        const uint32_t* Vs = Vst + p*KV_WORDS;

        float s[8][4];
#pragma unroll
        for (int nt = 0; nt < 8; nt++)
#pragma unroll
            for (int r = 0; r < 4; r++) s[nt][r] = 0.f;

#pragma unroll
        for (int k0 = 0; k0 < 64; k0 += 8) {
            uint32_t a[4];
            a[0] = Qs[r0*QP_STR + k0 + ig];
            a[1] = Qs[(r0+8)*QP_STR + k0 + ig];
            a[2] = Qs[r0*QP_STR + k0 + ig + 4];
            a[3] = Qs[(r0+8)*QP_STR + k0 + ig + 4];
            const int swk = g << 2;
#pragma unroll
            for (int nt = 0; nt < 8; nt++) {
                uint32_t b[2];
                b[0] = Ks[(nt*8+g)*KV_STR + ((k0 + ig) ^ swk)];
                b[1] = Ks[(nt*8+g)*KV_STR + ((k0 + ig + 4) ^ swk)];
                mma8(s[nt], a, b);
            }
        }

        if (jt == qt) {
            const int qa = q0 + r0, qb = qa + 8;
#pragma unroll
            for (int nt = 0; nt < 8; nt++) {
                const int j = j0 + nt*8 + 2*ig;
                if (j     > qa) s[nt][0] = -1e30f;
                if (j + 1 > qa) s[nt][1] = -1e30f;
                if (j     > qb) s[nt][2] = -1e30f;
                if (j + 1 > qb) s[nt][3] = -1e30f;
            }
        }

        float a0 = -1e30f, a1 = -1e30f;
#pragma unroll
        for (int nt = 0; nt < 8; nt++) {
            a0 = fmaxf(a0, fmaxf(s[nt][0], s[nt][1]));
            a1 = fmaxf(a1, fmaxf(s[nt][2], s[nt][3]));
        }
        a0 = fmaxf(a0, __shfl_xor_sync(0xFFFFFFFFu, a0, 1));
        a0 = fmaxf(a0, __shfl_xor_sync(0xFFFFFFFFu, a0, 2));
        a1 = fmaxf(a1, __shfl_xor_sync(0xFFFFFFFFu, a1, 1));
        a1 = fmaxf(a1, __shfl_xor_sync(0xFFFFFFFFu, a1, 2));

        const float mn0 = fmaxf(m0, a0), mn1 = fmaxf(m1, a1);
        const float c0 = __expf(m0 - mn0), c1 = __expf(m1 - mn1);
        l0 *= c0; l1 *= c1;
#pragma unroll
        for (int nt = 0; nt < 8; nt++) {
            O[nt][0] *= c0; O[nt][1] *= c0;
            O[nt][2] *= c1; O[nt][3] *= c1;
        }

        float t0 = 0.f, t1 = 0.f;
#pragma unroll
        for (int nt = 0; nt < 8; nt++) {
            const float p0 = __expf(s[nt][0] - mn0);
            const float p1 = __expf(s[nt][1] - mn0);
            const float p2 = __expf(s[nt][2] - mn1);
            const float p3 = __expf(s[nt][3] - mn1);
            t0 += p0 + p1; t1 += p2 + p3;
            *(uint2*)(Ps + r0*QP_STR + nt*8 + 2*ig)     = make_uint2(f2tf32(p0), f2tf32(p1));
            *(uint2*)(Ps + (r0+8)*QP_STR + nt*8 + 2*ig) = make_uint2(f2tf32(p2), f2tf32(p3));
        }
        t0 += __shfl_xor_sync(0xFFFFFFFFu, t0, 1);
        t0 += __shfl_xor_sync(0xFFFFFFFFu, t0, 2);
        t1 += __shfl_xor_sync(0xFFFFFFFFu, t1, 1);
        t1 += __shfl_xor_sync(0xFFFFFFFFu, t1, 2);
        l0 += t0; l1 += t1;
        m0 = mn0; m1 = mn1;
        __syncwarp();

#pragma unroll
        for (int k0 = 0; k0 < 64; k0 += 8) {
            uint32_t a[4];
            a[0] = Ps[r0*QP_STR + k0 + ig];
            a[1] = Ps[(r0+8)*QP_STR + k0 + ig];
            a[2] = Ps[r0*QP_STR + k0 + ig + 4];
            a[3] = Ps[(r0+8)*QP_STR + k0 + ig + 4];
#pragma unroll
            for (int nt = 0; nt < 8; nt++) {
                uint32_t b[2];
                b[0] = Vs[(k0+ig)*KV_STR + nt*8 + g];
                b[1] = Vs[(k0+ig+4)*KV_STR + nt*8 + g];
                mma8(O[nt], a, b);
            }
        }
        __syncwarp();
    }

    const float inv0 = 1.f / l0, inv1 = 1.f / l1;
    const int b = bh >> 4, h = bh & 15;
    uint32_t* base = (uint32_t*)g_att + ((size_t)(b*TSEQ + q0 + r0))*CDIM + h*DHEAD;
#pragma unroll
    for (int nt = 0; nt < 8; nt++) {
        *(uint2*)(base + nt*8 + 2*ig) =
            make_uint2(f2tf32(O[nt][0]*inv0), f2tf32(O[nt][1]*inv0));
        *(uint2*)(base + (size_t)8*CDIM + nt*8 + 2*ig) =
            make_uint2(f2tf32(O[nt][2]*inv1), f2tf32(O[nt][3]*inv1));
    }
}

// ---------------- launch ----------------
extern "C" void kernel_launch(void* const* d_in, const int* in_sizes, int n_in,
                              void* d_out, int out_size)
{
    (void)in_sizes; (void)n_in; (void)out_size;
    const float* x     = (const float*)d_in[0];
    const float* w_qkv = (const float*)d_in[1];
    const float* b_qkv = (const float*)d_in[2];
    const float* w_out = (const float*)d_in[3];
    const float* b_out = (const float*)d_in[4];
    float* out = (float*)d_out;

    cudaFuncSetAttribute(mm_kernel,   cudaFuncAttributeMaxDynamicSharedMemorySize, MM_SMEM);
    cudaFuncSetAttribute(attn_kernel, cudaFuncAttributeMaxDynamicSharedMemorySize, AT_SMEM);

    float *xt, *wq, *wo;
    cudaGetSymbolAddress((void**)&xt, g_xt);
    cudaGetSymbolAddress((void**)&wq, g_wq);
    cudaGetSymbolAddress((void**)&wo, g_wo);

    // 0) one-shot tf32 pre-conversion of external fp32 operands
    cvt_kernel<<<(MROWS*CDIM/4 + 255)/256, 256>>>((const float4*)x,     (uint4*)xt, MROWS*CDIM/4);
    cvt_kernel<<<(KDIM*3*CDIM/4 + 255)/256, 256>>>((const float4*)w_qkv, (uint4*)wq, KDIM*3*CDIM/4);
    cvt_kernel<<<(KDIM*CDIM/4   + 255)/256, 256>>>((const float4*)w_out, (uint4*)wo, KDIM*CDIM/4);

    // 1) QKV projection + bias + head-split scatter (tf32-bit Q/K/V, Q pre-scaled)
    mm_kernel<<<dim3(3072/128, MROWS/128), 128, MM_SMEM>>>(xt, wq, b_qkv, nullptr, 3072, 0);
    // 2) causal flash attention (cp.async double-buffered K/V)
    attn_kernel<<<dim3(TSEQ/64, BSZ*HH), 128, AT_SMEM>>>();
    // 3) output projection + bias (fp32 out)
    mm_kernel<<<dim3(1024/128, MROWS/128), 128, MM_SMEM>>>(nullptr, wo, b_out, out, 1024, 1);
}

// round 10
// speedup vs baseline: 8.0667x; 1.6039x over previous
#include <cuda_runtime.h>
#include <cuda_fp16.h>
#include <cstdint>

#define BSZ  4
#define TSEQ 2048
#define CDIM 1024
#define HH   16
#define DHEAD 64
#define MROWS (BSZ*TSEQ)   // 8192
#define KDIM 1024

// ---------------- device scratch (allocation-free rule), all fp16 ----------------
__device__ __align__(16) __half g_q[(size_t)BSZ*HH*TSEQ*DHEAD];
__device__ __align__(16) __half g_k[(size_t)BSZ*HH*TSEQ*DHEAD];
__device__ __align__(16) __half g_v[(size_t)BSZ*HH*TSEQ*DHEAD];
__device__ __align__(16) __half g_att[(size_t)MROWS*CDIM];
__device__ __align__(16) __half g_xt[(size_t)MROWS*CDIM];       // x, fp16
__device__ __align__(16) __half g_wq[(size_t)3*CDIM*KDIM];      // w_qkv^T [N][K] fp16
__device__ __align__(16) __half g_wo[(size_t)CDIM*KDIM];        // w_out^T [N][K] fp16

// ---------------- helpers ----------------
__device__ __forceinline__ void mma16(float* d, const uint32_t* a, const uint32_t* b) {
    asm("mma.sync.aligned.m16n8k16.row.col.f32.f16.f16.f32 "
        "{%0,%1,%2,%3}, {%4,%5,%6,%7}, {%8,%9}, {%0,%1,%2,%3};"
        : "+f"(d[0]), "+f"(d[1]), "+f"(d[2]), "+f"(d[3])
        : "r"(a[0]), "r"(a[1]), "r"(a[2]), "r"(a[3]), "r"(b[0]), "r"(b[1]));
}

__device__ __forceinline__ void ldsm4t(uint32_t& r0, uint32_t& r1, uint32_t& r2, uint32_t& r3,
                                       uint32_t addr) {
    asm volatile("ldmatrix.sync.aligned.m8n8.x4.trans.shared.b16 {%0,%1,%2,%3}, [%4];"
                 : "=r"(r0), "=r"(r1), "=r"(r2), "=r"(r3) : "r"(addr));
}

__device__ __forceinline__ uint32_t smem_u32(const void* p) {
    uint32_t a;
    asm("{ .reg .u64 t; cvta.to.shared.u64 t, %1; cvt.u32.u64 %0, t; }" : "=r"(a) : "l"(p));
    return a;
}

__device__ __forceinline__ void cp16(uint32_t s, const void* g) {
    asm volatile("cp.async.cg.shared.global [%0], [%1], 16;" :: "r"(s), "l"(g));
}
#define CP_COMMIT() asm volatile("cp.async.commit_group;" ::: "memory")
#define CP_WAIT1()  asm volatile("cp.async.wait_group 1;" ::: "memory")
#define CP_WAIT0()  asm volatile("cp.async.wait_group 0;" ::: "memory")

__device__ __forceinline__ uint32_t pack_h2(float a, float b) {
    __half2 h = __floats2half2_rn(a, b);
    return *(uint32_t*)&h;
}

// ---------------- x: f32 -> f16 ----------------
__global__ __launch_bounds__(256)
void cvtx_kernel(const float4* __restrict__ src, uint2* __restrict__ dst, int n4)
{
    const int i = blockIdx.x * 256 + threadIdx.x;
    if (i < n4) {
        float4 v = src[i];
        dst[i] = make_uint2(pack_h2(v.x, v.y), pack_h2(v.z, v.w));
    }
}

// ---------------- weight: f32 [R][C] -> f16 transposed [C][R] ----------------
__global__ __launch_bounds__(256)
void cvtw_kernel(const float* __restrict__ src, __half* __restrict__ dst, int R, int C)
{
    __shared__ float t[32][33];
    const int c0 = blockIdx.x * 32, r0 = blockIdx.y * 32;
    const int tx = threadIdx.x, ty = threadIdx.y;
#pragma unroll
    for (int i = 0; i < 4; i++)
        t[ty + 8*i][tx] = src[(size_t)(r0 + ty + 8*i) * C + c0 + tx];
    __syncthreads();
#pragma unroll
    for (int i = 0; i < 4; i++)
        dst[(size_t)(c0 + ty + 8*i) * R + r0 + tx] = __float2half_rn(t[tx][ty + 8*i]);
}

// ---------------- fp16 mma.sync GEMM, cp.async 3-stage ----------------
// C[M,N] = A[M,1024] @ Wt[N,1024]^T + bias. CTA 128x128, BK=32, 256 thr = 8 warps (2m x 4n).
// Smem rows stride 40 halves (80B): a-frags (20g+ig) and b-frags conflict-free.
#define BK 32
#define MA_STR 40
#define MA_H (128*MA_STR)               // A tile halves
#define MB_H (128*MA_STR)               // B tile halves ([n][k])
#define ST_H (MA_H + MB_H)              // 10240 halves = 20480 B
#define STAGES 3
#define MM_SMEM (STAGES*ST_H*2)         // 61440 B

__global__ __launch_bounds__(256, 2)
void mm_kernel(const __half* __restrict__ A, const __half* __restrict__ Bt,
               const float* __restrict__ bias, float* __restrict__ Cout,
               int N, int mode)
{
    extern __shared__ __half smh[];
    const uint32_t sb = smem_u32(smh);

    const int tid  = threadIdx.x;
    const int lane = tid & 31;
    const int warp = tid >> 5;
    const int wm = (warp >> 2) * 64;
    const int wn = (warp & 3) * 32;
    const int g  = lane >> 2;
    const int ig = lane & 3;

    const int m0 = blockIdx.y * 128;
    const int n0 = blockIdx.x * 128;

    if (mode) A = g_att;

    float d[4][4][4];
#pragma unroll
    for (int mt = 0; mt < 4; mt++)
#pragma unroll
        for (int nt = 0; nt < 4; nt++)
#pragma unroll
            for (int r = 0; r < 4; r++) d[mt][nt][r] = 0.f;

    // A tile: 128 rows x 32 halves (4 x 16B chunks/row): 512 cp16, 2/thread
    // B tile: 128 n-rows x 32 halves: 512 cp16, 2/thread
#define LDG_ASYNC(c, st) do {                                                     \
    uint32_t _sa = sb + (st)*ST_H*2;                                              \
    uint32_t _sb2 = _sa + MA_H*2;                                                 \
    _Pragma("unroll") for (int i = 0; i < 2; i++) {                               \
        int idx = tid + 256*i; int row = idx >> 2, c8 = idx & 3;                  \
        cp16(_sa + (row*MA_STR + c8*8)*2,                                         \
             A + (size_t)(m0 + row)*KDIM + (c)*BK + c8*8); }                      \
    _Pragma("unroll") for (int i = 0; i < 2; i++) {                               \
        int idx = tid + 256*i; int row = idx >> 2, c8 = idx & 3;                  \
        cp16(_sb2 + (row*MA_STR + c8*8)*2,                                        \
             Bt + (size_t)(n0 + row)*KDIM + (c)*BK + c8*8); }                     \
} while (0)

#define COMPUTE(st) do {                                                          \
    const __half* Ap = smh + (st)*ST_H;                                           \
    const __half* Bp = Ap + MA_H;                                                 \
    _Pragma("unroll") for (int s = 0; s < 2; s++) {                               \
        const int k0 = s*16;                                                      \
        uint32_t af[4][4], bf[4][2];                                              \
        _Pragma("unroll") for (int mt = 0; mt < 4; mt++) {                        \
            const int r = wm + mt*16 + g;                                         \
            af[mt][0] = *(const uint32_t*)(Ap + r*MA_STR + k0 + 2*ig);            \
            af[mt][1] = *(const uint32_t*)(Ap + (r+8)*MA_STR + k0 + 2*ig);        \
            af[mt][2] = *(const uint32_t*)(Ap + r*MA_STR + k0 + 8 + 2*ig);        \
            af[mt][3] = *(const uint32_t*)(Ap + (r+8)*MA_STR + k0 + 8 + 2*ig);    \
        }                                                                         \
        _Pragma("unroll") for (int nt = 0; nt < 4; nt++) {                        \
            const int nn = wn + nt*8 + g;                                         \
            bf[nt][0] = *(const uint32_t*)(Bp + nn*MA_STR + k0 + 2*ig);           \
            bf[nt][1] = *(const uint32_t*)(Bp + nn*MA_STR + k0 + 8 + 2*ig);       \
        }                                                                         \
        _Pragma("unroll") for (int mt = 0; mt < 4; mt++)                          \
            _Pragma("unroll") for (int nt = 0; nt < 4; nt++)                      \
                mma16(d[mt][nt], af[mt], bf[nt]);                                 \
    }                                                                             \
} while (0)

    LDG_ASYNC(0, 0); CP_COMMIT();
    LDG_ASYNC(1, 1); CP_COMMIT();

#pragma unroll 1
    for (int c = 0; c < KDIM/BK; c++) {
        CP_WAIT1();
        __syncthreads();
        if (c + 2 < KDIM/BK) {
            const int st = (c + 2) % STAGES;
            LDG_ASYNC(c + 2, st);
        }
        CP_COMMIT();
        COMPUTE(c % STAGES);
    }

#pragma unroll
    for (int mt = 0; mt < 4; mt++) {
        const int r0 = m0 + wm + mt*16 + g;
#pragma unroll
        for (int nt = 0; nt < 4; nt++) {
            const int c0 = n0 + wn + nt*8 + ig*2;
            const float b0 = bias[c0], b1 = bias[c0+1];
            if (mode == 0) {
                const int sec = c0 >> 10;
                const int h   = (c0 & 1023) >> 6;
                const int dd  = c0 & 63;
                __half* dstp = (sec == 0) ? g_q : ((sec == 1) ? g_k : g_v);
                const float scale = (sec == 0) ? 0.125f : 1.0f;
#pragma unroll
                for (int rr = 0; rr < 2; rr++) {
                    const int r = r0 + rr*8;
                    const int b = r >> 11, t = r & 2047;
                    uint32_t v = pack_h2((d[mt][nt][rr*2+0] + b0) * scale,
                                         (d[mt][nt][rr*2+1] + b1) * scale);
                    *(uint32_t*)(dstp + (((size_t)(b*HH + h))*TSEQ + t)*DHEAD + dd) = v;
                }
            } else {
#pragma unroll
                for (int rr = 0; rr < 2; rr++) {
                    const int r = r0 + rr*8;
                    float2 v = make_float2(d[mt][nt][rr*2+0] + b0, d[mt][nt][rr*2+1] + b1);
                    *(float2*)(Cout + (size_t)r*N + c0) = v;
                }
            }
        }
    }
}

// ---------------- fp16 tensor-core flash attention, cp.async double-buffered K/V ----------------
// Smem rows stride 72 halves (144B): a/K-frag banks 4g+ig distinct; ldmatrix V rows conflict-free.
#define AT_STR 72
#define T_H (64*AT_STR)                 // 4608 halves = 9216 B per tile
#define AT_SMEM ((6*T_H)*2)             // Q + P + 2K + 2V = 55296 B

__global__ __launch_bounds__(128, 3)
void attn_kernel()
{
    extern __shared__ __half smh[];
    __half* Qs  = smh;
    __half* Ps  = Qs + T_H;
    __half* Kst = Ps + T_H;              // 2 stages
    __half* Vst = Kst + 2*T_H;           // 2 stages
    const uint32_t sb_k = smem_u32(Kst);
    const uint32_t sb_v = smem_u32(Vst);

    const int tid  = threadIdx.x;
    const int lane = tid & 31;
    const int w    = tid >> 5;
    const int g    = lane >> 2;
    const int ig   = lane & 3;
    const int bh = blockIdx.y;
    const int qt = (gridDim.x - 1) - blockIdx.x;   // long blocks first
    const int q0 = qt * 64;

    const __half* Qg = g_q + (size_t)bh * TSEQ * DHEAD;
    const __half* Kg = g_k + (size_t)bh * TSEQ * DHEAD;
    const __half* Vg = g_v + (size_t)bh * TSEQ * DHEAD;

    // per-tensor tile: 64 rows x 8 chunks(16B) = 512 cp16; 128 thr -> 4/thread
#define PREFETCH_KV(j0, st) do {                                                  \
    uint32_t _kb = sb_k + (st)*T_H*2;                                             \
    uint32_t _vb = sb_v + (st)*T_H*2;                                             \
    _Pragma("unroll") for (int i = 0; i < 4; i++) {                               \
        int f = tid + 128*i; int row = f >> 3, c8 = f & 7;                        \
        cp16(_kb + (row*AT_STR + c8*8)*2, Kg + (size_t)((j0)+row)*DHEAD + c8*8);  \
        cp16(_vb + (row*AT_STR + c8*8)*2, Vg + (size_t)((j0)+row)*DHEAD + c8*8);  \
    }                                                                             \
} while (0)

    // Q tile: raw copy (already scaled fp16)
#pragma unroll
    for (int i = 0; i < 4; i++) {
        const int f = tid + 128*i;
        const int row = f >> 3, c8 = f & 7;
        *(uint4*)(Qs + row*AT_STR + c8*8) =
            *(const uint4*)(Qg + (size_t)(q0+row)*DHEAD + c8*8);
    }

    PREFETCH_KV(0, 0);
    CP_COMMIT();

    const int r0 = 16*w + g;
    float O[8][4];
#pragma unroll
    for (int nt = 0; nt < 8; nt++)
#pragma unroll
        for (int r = 0; r < 4; r++) O[nt][r] = 0.f;
    float m0 = -1e30f, m1 = -1e30f, l0 = 0.f, l1 = 0.f;

    // ldmatrix per-lane base offsets for V (computed once; stage offset added in loop)
    const int mi  = lane >> 3;                 // matrix index 0..3
    const int rin = lane & 7;
    const int v_row_off = ((mi & 1) ? 8 : 0) + rin;   // + k0
    const int v_col_off = (mi >> 1) ? 8 : 0;          // + nn*16

#pragma unroll 1
    for (int jt = 0; jt <= qt; jt++) {
        const int j0 = jt * 64;
        const int p = jt & 1;

        CP_WAIT0();
        __syncthreads();

        if (jt < qt) {
            PREFETCH_KV(j0 + 64, p ^ 1);
            CP_COMMIT();
        }

        const __half* Ks = Kst + p*T_H;
        const uint32_t vbase = sb_v + p*T_H*2;

        // S = Q K^T  (16x64 per warp), k over DHEAD in steps of 16
        float s[8][4];
#pragma unroll
        for (int nt = 0; nt < 8; nt++)
#pragma unroll
            for (int r = 0; r < 4; r++) s[nt][r] = 0.f;

#pragma unroll
        for (int k0 = 0; k0 < 64; k0 += 16) {
            uint32_t a[4];
            a[0] = *(const uint32_t*)(Qs + r0*AT_STR + k0 + 2*ig);
            a[1] = *(const uint32_t*)(Qs + (r0+8)*AT_STR + k0 + 2*ig);
            a[2] = *(const uint32_t*)(Qs + r0*AT_STR + k0 + 8 + 2*ig);
            a[3] = *(const uint32_t*)(Qs + (r0+8)*AT_STR + k0 + 8 + 2*ig);
#pragma unroll
            for (int nt = 0; nt < 8; nt++) {
                uint32_t b[2];
                b[0] = *(const uint32_t*)(Ks + (nt*8+g)*AT_STR + k0 + 2*ig);
                b[1] = *(const uint32_t*)(Ks + (nt*8+g)*AT_STR + k0 + 8 + 2*ig);
                mma16(s[nt], a, b);
            }
        }

        if (jt == qt) {
            const int qa = q0 + r0, qb = qa + 8;
#pragma unroll
            for (int nt = 0; nt < 8; nt++) {
                const int j = j0 + nt*8 + 2*ig;
                if (j     > qa) s[nt][0] = -1e30f;
                if (j + 1 > qa) s[nt][1] = -1e30f;
                if (j     > qb) s[nt][2] = -1e30f;
                if (j + 1 > qb) s[nt][3] = -1e30f;
            }
        }

        float a0 = -1e30f, a1 = -1e30f;
#pragma unroll
        for (int nt = 0; nt < 8; nt++) {
            a0 = fmaxf(a0, fmaxf(s[nt][0], s[nt][1]));
            a1 = fmaxf(a1, fmaxf(s[nt][2], s[nt][3]));
        }
        a0 = fmaxf(a0, __shfl_xor_sync(0xFFFFFFFFu, a0, 1));
        a0 = fmaxf(a0, __shfl_xor_sync(0xFFFFFFFFu, a0, 2));
        a1 = fmaxf(a1, __shfl_xor_sync(0xFFFFFFFFu, a1, 1));
        a1 = fmaxf(a1, __shfl_xor_sync(0xFFFFFFFFu, a1, 2));

        const float mn0 = fmaxf(m0, a0), mn1 = fmaxf(m1, a1);
        const float c0 = __expf(m0 - mn0), c1 = __expf(m1 - mn1);
        l0 *= c0; l1 *= c1;
#pragma unroll
        for (int nt = 0; nt < 8; nt++) {
            O[nt][0] *= c0; O[nt][1] *= c0;
            O[nt][2] *= c1; O[nt][3] *= c1;
        }

        float t0 = 0.f, t1 = 0.f;
#pragma unroll
        for (int nt = 0; nt < 8; nt++) {
            const float p0 = __expf(s[nt][0] - mn0);
            const float p1 = __expf(s[nt][1] - mn0);
            const float p2 = __expf(s[nt][2] - mn1);
            const float p3 = __expf(s[nt][3] - mn1);
            t0 += p0 + p1; t1 += p2 + p3;
            *(uint32_t*)(Ps + r0*AT_STR + nt*8 + 2*ig)     = pack_h2(p0, p1);
            *(uint32_t*)(Ps + (r0+8)*AT_STR + nt*8 + 2*ig) = pack_h2(p2, p3);
        }
        t0 += __shfl_xor_sync(0xFFFFFFFFu, t0, 1);
        t0 += __shfl_xor_sync(0xFFFFFFFFu, t0, 2);
        t1 += __shfl_xor_sync(0xFFFFFFFFu, t1, 1);
        t1 += __shfl_xor_sync(0xFFFFFFFFu, t1, 2);
        l0 += t0; l1 += t1;
        m0 = mn0; m1 = mn1;
        __syncwarp();

        // O += P @ V : k over keys (steps of 16), V b-frags via ldmatrix.x4.trans
#pragma unroll
        for (int k0 = 0; k0 < 64; k0 += 16) {
            uint32_t a[4];
            a[0] = *(const uint32_t*)(Ps + r0*AT_STR + k0 + 2*ig);
            a[1] = *(const uint32_t*)(Ps + (r0+8)*AT_STR + k0 + 2*ig);
            a[2] = *(const uint32_t*)(Ps + r0*AT_STR + k0 + 8 + 2*ig);
            a[3] = *(const uint32_t*)(Ps + (r0+8)*AT_STR + k0 + 8 + 2*ig);
#pragma unroll
            for (int nn = 0; nn < 4; nn++) {
                uint32_t b0, b1, b2, b3;
                ldsm4t(b0, b1, b2, b3,
                       vbase + ((k0 + v_row_off)*AT_STR + nn*16 + v_col_off)*2);
                uint32_t bA[2] = { b0, b1 };
                uint32_t bB[2] = { b2, b3 };
                mma16(O[2*nn],   a, bA);
                mma16(O[2*nn+1], a, bB);
            }
        }
        __syncwarp();
    }

    // normalize, write g_att as fp16
    const float inv0 = 1.f / l0, inv1 = 1.f / l1;
    const int b = bh >> 4, h = bh & 15;
    __half* base = g_att + ((size_t)(b*TSEQ + q0 + r0))*CDIM + h*DHEAD;
#pragma unroll
    for (int nt = 0; nt < 8; nt++) {
        *(uint32_t*)(base + nt*8 + 2*ig) =
            pack_h2(O[nt][0]*inv0, O[nt][1]*inv0);
        *(uint32_t*)(base + (size_t)8*CDIM + nt*8 + 2*ig) =
            pack_h2(O[nt][2]*inv1, O[nt][3]*inv1);
    }
}

// ---------------- launch ----------------
extern "C" void kernel_launch(void* const* d_in, const int* in_sizes, int n_in,
                              void* d_out, int out_size)
{
    (void)in_sizes; (void)n_in; (void)out_size;
    const float* x     = (const float*)d_in[0];
    const float* w_qkv = (const float*)d_in[1];
    const float* b_qkv = (const float*)d_in[2];
    const float* w_out = (const float*)d_in[3];
    const float* b_out = (const float*)d_in[4];
    float* out = (float*)d_out;

    cudaFuncSetAttribute(mm_kernel,   cudaFuncAttributeMaxDynamicSharedMemorySize, MM_SMEM);
    cudaFuncSetAttribute(attn_kernel, cudaFuncAttributeMaxDynamicSharedMemorySize, AT_SMEM);

    __half *xt, *wq, *wo;
    cudaGetSymbolAddress((void**)&xt, g_xt);
    cudaGetSymbolAddress((void**)&wq, g_wq);
    cudaGetSymbolAddress((void**)&wo, g_wo);

    // 0) one-shot fp16 conversion (x) and transpose+conversion (weights -> [N][K])
    cvtx_kernel<<<(MROWS*CDIM/4 + 255)/256, 256>>>((const float4*)x, (uint2*)xt, MROWS*CDIM/4);
    cvtw_kernel<<<dim3(3072/32, 1024/32), dim3(32, 8)>>>(w_qkv, wq, 1024, 3072);
    cvtw_kernel<<<dim3(1024/32, 1024/32), dim3(32, 8)>>>(w_out, wo, 1024, 1024);

    // 1) QKV projection + bias + head-split scatter (fp16 Q/K/V, Q pre-scaled)
    mm_kernel<<<dim3(3072/128, MROWS/128), 256, MM_SMEM>>>(xt, wq, b_qkv, nullptr, 3072, 0);
    // 2) causal flash attention (fp16, cp.async double-buffered K/V)
    attn_kernel<<<dim3(TSEQ/64, BSZ*HH), 128, AT_SMEM>>>();
    // 3) output projection + bias (fp32 out)
    mm_kernel<<<dim3(1024/128, MROWS/128), 256, MM_SMEM>>>(nullptr, wo, b_out, out, 1024, 1);
}

// round 11
// speedup vs baseline: 8.5254x; 1.0569x over previous
#include <cuda_runtime.h>
#include <cuda_fp16.h>
#include <cstdint>

#define BSZ  4
#define TSEQ 2048
#define CDIM 1024
#define HH   16
#define DHEAD 64
#define MROWS (BSZ*TSEQ)   // 8192
#define KDIM 1024

// ---------------- device scratch (allocation-free rule), all fp16 ----------------
__device__ __align__(16) __half g_q[(size_t)BSZ*HH*TSEQ*DHEAD];
__device__ __align__(16) __half g_k[(size_t)BSZ*HH*TSEQ*DHEAD];
__device__ __align__(16) __half g_v[(size_t)BSZ*HH*TSEQ*DHEAD];
__device__ __align__(16) __half g_att[(size_t)MROWS*CDIM];
__device__ __align__(16) __half g_xt[(size_t)MROWS*CDIM];       // x, fp16
__device__ __align__(16) __half g_wq[(size_t)3*CDIM*KDIM];      // w_qkv^T [N][K] fp16
__device__ __align__(16) __half g_wo[(size_t)CDIM*KDIM];        // w_out^T [N][K] fp16

// ---------------- helpers ----------------
__device__ __forceinline__ void mma16(float* d, const uint32_t* a, const uint32_t* b) {
    asm("mma.sync.aligned.m16n8k16.row.col.f32.f16.f16.f32 "
        "{%0,%1,%2,%3}, {%4,%5,%6,%7}, {%8,%9}, {%0,%1,%2,%3};"
        : "+f"(d[0]), "+f"(d[1]), "+f"(d[2]), "+f"(d[3])
        : "r"(a[0]), "r"(a[1]), "r"(a[2]), "r"(a[3]), "r"(b[0]), "r"(b[1]));
}

__device__ __forceinline__ void ldsm4(uint32_t& r0, uint32_t& r1, uint32_t& r2, uint32_t& r3,
                                      uint32_t addr) {
    asm volatile("ldmatrix.sync.aligned.m8n8.x4.shared.b16 {%0,%1,%2,%3}, [%4];"
                 : "=r"(r0), "=r"(r1), "=r"(r2), "=r"(r3) : "r"(addr));
}

__device__ __forceinline__ void ldsm4t(uint32_t& r0, uint32_t& r1, uint32_t& r2, uint32_t& r3,
                                       uint32_t addr) {
    asm volatile("ldmatrix.sync.aligned.m8n8.x4.trans.shared.b16 {%0,%1,%2,%3}, [%4];"
                 : "=r"(r0), "=r"(r1), "=r"(r2), "=r"(r3) : "r"(addr));
}

__device__ __forceinline__ uint32_t smem_u32(const void* p) {
    uint32_t a;
    asm("{ .reg .u64 t; cvta.to.shared.u64 t, %1; cvt.u32.u64 %0, t; }" : "=r"(a) : "l"(p));
    return a;
}

__device__ __forceinline__ void cp16(uint32_t s, const void* g) {
    asm volatile("cp.async.cg.shared.global [%0], [%1], 16;" :: "r"(s), "l"(g));
}
#define CP_COMMIT() asm volatile("cp.async.commit_group;" ::: "memory")
#define CP_WAIT1()  asm volatile("cp.async.wait_group 1;" ::: "memory")
#define CP_WAIT0()  asm volatile("cp.async.wait_group 0;" ::: "memory")

__device__ __forceinline__ uint32_t pack_h2(float a, float b) {
    __half2 h = __floats2half2_rn(a, b);
    return *(uint32_t*)&h;
}

// ---------------- x: f32 -> f16 ----------------
__global__ __launch_bounds__(256)
void cvtx_kernel(const float4* __restrict__ src, uint2* __restrict__ dst, int n4)
{
    const int i = blockIdx.x * 256 + threadIdx.x;
    if (i < n4) {
        float4 v = src[i];
        dst[i] = make_uint2(pack_h2(v.x, v.y), pack_h2(v.z, v.w));
    }
}

// ---------------- weight: f32 [R][C] -> f16 transposed [C][R] ----------------
__global__ __launch_bounds__(256)
void cvtw_kernel(const float* __restrict__ src, __half* __restrict__ dst, int R, int C)
{
    __shared__ float t[32][33];
    const int c0 = blockIdx.x * 32, r0 = blockIdx.y * 32;
    const int tx = threadIdx.x, ty = threadIdx.y;
#pragma unroll
    for (int i = 0; i < 4; i++)
        t[ty + 8*i][tx] = src[(size_t)(r0 + ty + 8*i) * C + c0 + tx];
    __syncthreads();
#pragma unroll
    for (int i = 0; i < 4; i++)
        dst[(size_t)(c0 + ty + 8*i) * R + r0 + tx] = __float2half_rn(t[tx][ty + 8*i]);
}

// ---------------- fp16 mma.sync GEMM: ldmatrix + BK=64, cp.async 3-stage ----------------
// C[M,N] = A[M,1024] @ Wt[N,1024]^T + bias. CTA 128x128, BK=64, 256 thr = 8 warps (2m x 4n).
// Smem rows stride 72 halves (144B): LDSM phases conflict-free (rows rotate banks by 4).
#define BK 64
#define MA_STR 72
#define MA_H (128*MA_STR)               // 9216 halves per tile
#define ST_H (2*MA_H)                   // 18432 halves = 36864 B
#define STAGES 3
#define MM_SMEM (STAGES*ST_H*2)         // 110592 B

__global__ __launch_bounds__(256, 2)
void mm_kernel(const __half* __restrict__ A, const __half* __restrict__ Bt,
               const float* __restrict__ bias, float* __restrict__ Cout,
               int N, int mode)
{
    extern __shared__ __half smh[];
    const uint32_t sb = smem_u32(smh);

    const int tid  = threadIdx.x;
    const int lane = tid & 31;
    const int warp = tid >> 5;
    const int wm = (warp >> 2) * 64;
    const int wn = (warp & 3) * 32;
    const int g  = lane >> 2;
    const int ig = lane & 3;

    const int m0 = blockIdx.y * 128;
    const int n0 = blockIdx.x * 128;

    if (mode) A = g_att;

    // per-lane ldmatrix offsets (halves -> bytes)
    const uint32_t aoff = ((wm + (lane & 15)) * MA_STR + (lane >> 4) * 8) * 2;
    const uint32_t boff = ((wn + (lane & 15)) * MA_STR + (lane >> 4) * 8) * 2;

    float d[4][4][4];
#pragma unroll
    for (int mt = 0; mt < 4; mt++)
#pragma unroll
        for (int nt = 0; nt < 4; nt++)
#pragma unroll
            for (int r = 0; r < 4; r++) d[mt][nt][r] = 0.f;

    // A tile: 128 rows x 64 halves = 8 x 16B chunks/row -> 1024 cp16; B same; 8/thread
#define LDG_ASYNC(c, st) do {                                                     \
    uint32_t _sa = sb + (st)*ST_H*2;                                              \
    uint32_t _sb2 = _sa + MA_H*2;                                                 \
    _Pragma("unroll") for (int i = 0; i < 4; i++) {                               \
        int idx = tid + 256*i; int row = idx >> 3, c8 = idx & 7;                  \
        cp16(_sa + (row*MA_STR + c8*8)*2,                                         \
             A + (size_t)(m0 + row)*KDIM + (c)*BK + c8*8); }                      \
    _Pragma("unroll") for (int i = 0; i < 4; i++) {                               \
        int idx = tid + 256*i; int row = idx >> 3, c8 = idx & 7;                  \
        cp16(_sb2 + (row*MA_STR + c8*8)*2,                                        \
             Bt + (size_t)(n0 + row)*KDIM + (c)*BK + c8*8); }                     \
} while (0)

#define COMPUTE(st) do {                                                          \
    const uint32_t _ab = sb + (st)*ST_H*2 + aoff;                                 \
    const uint32_t _bb = sb + (st)*ST_H*2 + MA_H*2 + boff;                        \
    _Pragma("unroll") for (int s = 0; s < 4; s++) {                               \
        const int k0 = s*16;                                                      \
        uint32_t af[4][4], bf[2][4];                                              \
        _Pragma("unroll") for (int mt = 0; mt < 4; mt++)                          \
            ldsm4(af[mt][0], af[mt][1], af[mt][2], af[mt][3],                     \
                  _ab + (mt*16*MA_STR + k0)*2);                                   \
        _Pragma("unroll") for (int p = 0; p < 2; p++)                             \
            ldsm4(bf[p][0], bf[p][1], bf[p][2], bf[p][3],                         \
                  _bb + (p*16*MA_STR + k0)*2);                                    \
        _Pragma("unroll") for (int mt = 0; mt < 4; mt++)                          \
            _Pragma("unroll") for (int p = 0; p < 2; p++) {                       \
                uint32_t b0[2] = { bf[p][0], bf[p][2] };                          \
                uint32_t b1[2] = { bf[p][1], bf[p][3] };                          \
                mma16(d[mt][2*p],   af[mt], b0);                                  \
                mma16(d[mt][2*p+1], af[mt], b1);                                  \
            }                                                                     \
    }                                                                             \
} while (0)

    LDG_ASYNC(0, 0); CP_COMMIT();
    LDG_ASYNC(1, 1); CP_COMMIT();

#pragma unroll 1
    for (int c = 0; c < KDIM/BK; c++) {
        CP_WAIT1();
        __syncthreads();
        if (c + 2 < KDIM/BK) {
            const int st = (c + 2) % STAGES;
            LDG_ASYNC(c + 2, st);
        }
        CP_COMMIT();
        COMPUTE(c % STAGES);
    }

#pragma unroll
    for (int mt = 0; mt < 4; mt++) {
        const int r0 = m0 + wm + mt*16 + g;
#pragma unroll
        for (int nt = 0; nt < 4; nt++) {
            const int c0 = n0 + wn + nt*8 + ig*2;
            const float b0 = bias[c0], b1 = bias[c0+1];
            if (mode == 0) {
                const int sec = c0 >> 10;
                const int h   = (c0 & 1023) >> 6;
                const int dd  = c0 & 63;
                __half* dstp = (sec == 0) ? g_q : ((sec == 1) ? g_k : g_v);
                const float scale = (sec == 0) ? 0.125f : 1.0f;
#pragma unroll
                for (int rr = 0; rr < 2; rr++) {
                    const int r = r0 + rr*8;
                    const int b = r >> 11, t = r & 2047;
                    uint32_t v = pack_h2((d[mt][nt][rr*2+0] + b0) * scale,
                                         (d[mt][nt][rr*2+1] + b1) * scale);
                    *(uint32_t*)(dstp + (((size_t)(b*HH + h))*TSEQ + t)*DHEAD + dd) = v;
                }
            } else {
#pragma unroll
                for (int rr = 0; rr < 2; rr++) {
                    const int r = r0 + rr*8;
                    float2 v = make_float2(d[mt][nt][rr*2+0] + b0, d[mt][nt][rr*2+1] + b1);
                    *(float2*)(Cout + (size_t)r*N + c0) = v;
                }
            }
        }
    }
}

// ---------------- fp16 tensor-core flash attention (unchanged from R10) ----------------
#define AT_STR 72
#define T_H (64*AT_STR)                 // 4608 halves = 9216 B per tile
#define AT_SMEM ((6*T_H)*2)             // Q + P + 2K + 2V = 55296 B

__global__ __launch_bounds__(128, 3)
void attn_kernel()
{
    extern __shared__ __half smh[];
    __half* Qs  = smh;
    __half* Ps  = Qs + T_H;
    __half* Kst = Ps + T_H;
    __half* Vst = Kst + 2*T_H;
    const uint32_t sb_k = smem_u32(Kst);
    const uint32_t sb_v = smem_u32(Vst);

    const int tid  = threadIdx.x;
    const int lane = tid & 31;
    const int w    = tid >> 5;
    const int g    = lane >> 2;
    const int ig   = lane & 3;
    const int bh = blockIdx.y;
    const int qt = (gridDim.x - 1) - blockIdx.x;
    const int q0 = qt * 64;

    const __half* Qg = g_q + (size_t)bh * TSEQ * DHEAD;
    const __half* Kg = g_k + (size_t)bh * TSEQ * DHEAD;
    const __half* Vg = g_v + (size_t)bh * TSEQ * DHEAD;

#define PREFETCH_KV(j0, st) do {                                                  \
    uint32_t _kb = sb_k + (st)*T_H*2;                                             \
    uint32_t _vb = sb_v + (st)*T_H*2;                                             \
    _Pragma("unroll") for (int i = 0; i < 4; i++) {                               \
        int f = tid + 128*i; int row = f >> 3, c8 = f & 7;                        \
        cp16(_kb + (row*AT_STR + c8*8)*2, Kg + (size_t)((j0)+row)*DHEAD + c8*8);  \
        cp16(_vb + (row*AT_STR + c8*8)*2, Vg + (size_t)((j0)+row)*DHEAD + c8*8);  \
    }                                                                             \
} while (0)

#pragma unroll
    for (int i = 0; i < 4; i++) {
        const int f = tid + 128*i;
        const int row = f >> 3, c8 = f & 7;
        *(uint4*)(Qs + row*AT_STR + c8*8) =
            *(const uint4*)(Qg + (size_t)(q0+row)*DHEAD + c8*8);
    }

    PREFETCH_KV(0, 0);
    CP_COMMIT();

    const int r0 = 16*w + g;
    float O[8][4];
#pragma unroll
    for (int nt = 0; nt < 8; nt++)
#pragma unroll
        for (int r = 0; r < 4; r++) O[nt][r] = 0.f;
    float m0 = -1e30f, m1 = -1e30f, l0 = 0.f, l1 = 0.f;

    const int mi  = lane >> 3;
    const int rin = lane & 7;
    const int v_row_off = ((mi & 1) ? 8 : 0) + rin;
    const int v_col_off = (mi >> 1) ? 8 : 0;

#pragma unroll 1
    for (int jt = 0; jt <= qt; jt++) {
        const int j0 = jt * 64;
        const int p = jt & 1;

        CP_WAIT0();
        __syncthreads();

        if (jt < qt) {
            PREFETCH_KV(j0 + 64, p ^ 1);
            CP_COMMIT();
        }

        const __half* Ks = Kst + p*T_H;
        const uint32_t vbase = sb_v + p*T_H*2;

        float s[8][4];
#pragma unroll
        for (int nt = 0; nt < 8; nt++)
#pragma unroll
            for (int r = 0; r < 4; r++) s[nt][r] = 0.f;

#pragma unroll
        for (int k0 = 0; k0 < 64; k0 += 16) {
            uint32_t a[4];
            a[0] = *(const uint32_t*)(Qs + r0*AT_STR + k0 + 2*ig);
            a[1] = *(const uint32_t*)(Qs + (r0+8)*AT_STR + k0 + 2*ig);
            a[2] = *(const uint32_t*)(Qs + r0*AT_STR + k0 + 8 + 2*ig);
            a[3] = *(const uint32_t*)(Qs + (r0+8)*AT_STR + k0 + 8 + 2*ig);
#pragma unroll
            for (int nt = 0; nt < 8; nt++) {
                uint32_t b[2];
                b[0] = *(const uint32_t*)(Ks + (nt*8+g)*AT_STR + k0 + 2*ig);
                b[1] = *(const uint32_t*)(Ks + (nt*8+g)*AT_STR + k0 + 8 + 2*ig);
                mma16(s[nt], a, b);
            }
        }

        if (jt == qt) {
            const int qa = q0 + r0, qb = qa + 8;
#pragma unroll
            for (int nt = 0; nt < 8; nt++) {
                const int j = j0 + nt*8 + 2*ig;
                if (j     > qa) s[nt][0] = -1e30f;
                if (j + 1 > qa) s[nt][1] = -1e30f;
                if (j     > qb) s[nt][2] = -1e30f;
                if (j + 1 > qb) s[nt][3] = -1e30f;
            }
        }

        float a0 = -1e30f, a1 = -1e30f;
#pragma unroll
        for (int nt = 0; nt < 8; nt++) {
            a0 = fmaxf(a0, fmaxf(s[nt][0], s[nt][1]));
            a1 = fmaxf(a1, fmaxf(s[nt][2], s[nt][3]));
        }
        a0 = fmaxf(a0, __shfl_xor_sync(0xFFFFFFFFu, a0, 1));
        a0 = fmaxf(a0, __shfl_xor_sync(0xFFFFFFFFu, a0, 2));
        a1 = fmaxf(a1, __shfl_xor_sync(0xFFFFFFFFu, a1, 1));
        a1 = fmaxf(a1, __shfl_xor_sync(0xFFFFFFFFu, a1, 2));

        const float mn0 = fmaxf(m0, a0), mn1 = fmaxf(m1, a1);
        const float c0 = __expf(m0 - mn0), c1 = __expf(m1 - mn1);
        l0 *= c0; l1 *= c1;
#pragma unroll
        for (int nt = 0; nt < 8; nt++) {
            O[nt][0] *= c0; O[nt][1] *= c0;
            O[nt][2] *= c1; O[nt][3] *= c1;
        }

        float t0 = 0.f, t1 = 0.f;
#pragma unroll
        for (int nt = 0; nt < 8; nt++) {
            const float p0 = __expf(s[nt][0] - mn0);
            const float p1 = __expf(s[nt][1] - mn0);
            const float p2 = __expf(s[nt][2] - mn1);
            const float p3 = __expf(s[nt][3] - mn1);
            t0 += p0 + p1; t1 += p2 + p3;
            *(uint32_t*)(Ps + r0*AT_STR + nt*8 + 2*ig)     = pack_h2(p0, p1);
            *(uint32_t*)(Ps + (r0+8)*AT_STR + nt*8 + 2*ig) = pack_h2(p2, p3);
        }
        t0 += __shfl_xor_sync(0xFFFFFFFFu, t0, 1);
        t0 += __shfl_xor_sync(0xFFFFFFFFu, t0, 2);
        t1 += __shfl_xor_sync(0xFFFFFFFFu, t1, 1);
        t1 += __shfl_xor_sync(0xFFFFFFFFu, t1, 2);
        l0 += t0; l1 += t1;
        m0 = mn0; m1 = mn1;
        __syncwarp();

#pragma unroll
        for (int k0 = 0; k0 < 64; k0 += 16) {
            uint32_t a[4];
            a[0] = *(const uint32_t*)(Ps + r0*AT_STR + k0 + 2*ig);
            a[1] = *(const uint32_t*)(Ps + (r0+8)*AT_STR + k0 + 2*ig);
            a[2] = *(const uint32_t*)(Ps + r0*AT_STR + k0 + 8 + 2*ig);
            a[3] = *(const uint32_t*)(Ps + (r0+8)*AT_STR + k0 + 8 + 2*ig);
#pragma unroll
            for (int nn = 0; nn < 4; nn++) {
                uint32_t b0, b1, b2, b3;
                ldsm4t(b0, b1, b2, b3,
                       vbase + ((k0 + v_row_off)*AT_STR + nn*16 + v_col_off)*2);
                uint32_t bA[2] = { b0, b1 };
                uint32_t bB[2] = { b2, b3 };
                mma16(O[2*nn],   a, bA);
                mma16(O[2*nn+1], a, bB);
            }
        }
        __syncwarp();
    }

    const float inv0 = 1.f / l0, inv1 = 1.f / l1;
    const int b = bh >> 4, h = bh & 15;
    __half* base = g_att + ((size_t)(b*TSEQ + q0 + r0))*CDIM + h*DHEAD;
#pragma unroll
    for (int nt = 0; nt < 8; nt++) {
        *(uint32_t*)(base + nt*8 + 2*ig) =
            pack_h2(O[nt][0]*inv0, O[nt][1]*inv0);
        *(uint32_t*)(base + (size_t)8*CDIM + nt*8 + 2*ig) =
            pack_h2(O[nt][2]*inv1, O[nt][3]*inv1);
    }
}

// ---------------- launch ----------------
extern "C" void kernel_launch(void* const* d_in, const int* in_sizes, int n_in,
                              void* d_out, int out_size)
{
    (void)in_sizes; (void)n_in; (void)out_size;
    const float* x     = (const float*)d_in[0];
    const float* w_qkv = (const float*)d_in[1];
    const float* b_qkv = (const float*)d_in[2];
    const float* w_out = (const float*)d_in[3];
    const float* b_out = (const float*)d_in[4];
    float* out = (float*)d_out;

    cudaFuncSetAttribute(mm_kernel,   cudaFuncAttributeMaxDynamicSharedMemorySize, MM_SMEM);
    cudaFuncSetAttribute(attn_kernel, cudaFuncAttributeMaxDynamicSharedMemorySize, AT_SMEM);

    __half *xt, *wq, *wo;
    cudaGetSymbolAddress((void**)&xt, g_xt);
    cudaGetSymbolAddress((void**)&wq, g_wq);
    cudaGetSymbolAddress((void**)&wo, g_wo);

    // 0) one-shot fp16 conversion (x) and transpose+conversion (weights -> [N][K])
    cvtx_kernel<<<(MROWS*CDIM/4 + 255)/256, 256>>>((const float4*)x, (uint2*)xt, MROWS*CDIM/4);
    cvtw_kernel<<<dim3(3072/32, 1024/32), dim3(32, 8)>>>(w_qkv, wq, 1024, 3072);
    cvtw_kernel<<<dim3(1024/32, 1024/32), dim3(32, 8)>>>(w_out, wo, 1024, 1024);

    // 1) QKV projection + bias + head-split scatter (fp16 Q/K/V, Q pre-scaled)
    mm_kernel<<<dim3(3072/128, MROWS/128), 256, MM_SMEM>>>(xt, wq, b_qkv, nullptr, 3072, 0);
    // 2) causal flash attention (fp16, cp.async double-buffered K/V)
    attn_kernel<<<dim3(TSEQ/64, BSZ*HH), 128, AT_SMEM>>>();
    // 3) output projection + bias (fp32 out)
    mm_kernel<<<dim3(1024/128, MROWS/128), 256, MM_SMEM>>>(nullptr, wo, b_out, out, 1024, 1);
}